// round 11
// baseline (speedup 1.0000x reference)
#include <cuda_runtime.h>
#include <cuda_bf16.h>
#include <math.h>
#include <stdint.h>

#define N_ROWS 3456      // 16 * 216
#define C_DIM  256
#define K_CODES 1024
#define B_SZ   16
#define SPAT   216       // 6*6*6
#define VOX    13824     // 24^3
#define OUT_ZQ (B_SZ * C_DIM * SPAT)   // 884736
#define OUT_LOSS OUT_ZQ
#define OUT_IDX (OUT_ZQ + 1)

// ---------------- device scratch ----------------
__device__ float g_zn[N_ROWS * C_DIM];
__device__ __nv_bfloat16 g_z0[N_ROWS * C_DIM];
__device__ __nv_bfloat16 g_z1[N_ROWS * C_DIM];
__device__ float g_en[K_CODES * C_DIM];
__device__ __nv_bfloat16 g_e0[K_CODES * C_DIM];
__device__ __nv_bfloat16 g_e1[K_CODES * C_DIM];
__device__ float g_aff[N_ROWS * K_CODES];
__device__ unsigned long long g_pat[N_ROWS];
__device__ float g_avgp[K_CODES];
__device__ float g_sums[8];   // 0: SSE, 1: entropy sum, 2: sumW, 3: sumWcos
__device__ int g_ctr;

// ---------------- helpers ----------------
__device__ __forceinline__ float bsum256(float v, float* red) {
    #pragma unroll
    for (int o = 16; o; o >>= 1) v += __shfl_xor_sync(0xffffffffu, v, o);
    __syncthreads();
    if ((threadIdx.x & 31) == 0) red[threadIdx.x >> 5] = v;
    __syncthreads();
    float s = 0.f;
    #pragma unroll
    for (int w = 0; w < 8; w++) s += red[w];
    return s;
}

__device__ __forceinline__ float fexp(float d) {   // e^d for d <= 0
    float r;
    asm("ex2.approx.f32 %0, %1;" : "=f"(r) : "f"(d * 1.4426950408889634f));
    return r;
}

__device__ __forceinline__ void ldsm_x4(uint32_t& r0, uint32_t& r1, uint32_t& r2, uint32_t& r3, uint32_t addr) {
    asm volatile("ldmatrix.sync.aligned.m8n8.x4.shared.b16 {%0,%1,%2,%3}, [%4];"
                 : "=r"(r0), "=r"(r1), "=r"(r2), "=r"(r3) : "r"(addr));
}
__device__ __forceinline__ void mma_bf16(float* c, uint32_t a0, uint32_t a1, uint32_t a2, uint32_t a3,
                                         uint32_t b0, uint32_t b1) {
    asm volatile("mma.sync.aligned.m16n8k16.row.col.f32.bf16.bf16.f32 "
                 "{%0,%1,%2,%3}, {%4,%5,%6,%7}, {%8,%9}, {%0,%1,%2,%3};"
                 : "+f"(c[0]), "+f"(c[1]), "+f"(c[2]), "+f"(c[3])
                 : "r"(a0), "r"(a1), "r"(a2), "r"(a3), "r"(b0), "r"(b1));
}

__device__ __forceinline__ void bsplit2(float x, __nv_bfloat16& b0, __nv_bfloat16& b1) {
    b0 = __float2bfloat16_rn(x);
    b1 = __float2bfloat16_rn(x - __bfloat162float(b0));
}

// =======================================================================
// K_PRE: pattern (blocks 0..431) | norm_z (432..559) | norm_cb (560..1583)
// =======================================================================
#define NZ_SCH 27
#define NZ_PAD 29
#define PRE_NZ_BYTES (256 * NZ_PAD * 4 + 8 * 32 * 4 + NZ_SCH * 4 + 64)
__global__ __launch_bounds__(256) void k_pre(const float* __restrict__ inp,
                                             const float* __restrict__ z_e,
                                             const float* __restrict__ cb) {
    __shared__ __align__(16) char sraw[PRE_NZ_BYTES];
    int tid = threadIdx.x;
    int bid = blockIdx.x;

    if (bid < 432) {
        // ---- patterns: 2 voxels/thread, 8 patterns/block ----
        unsigned char* sb = (unsigned char*)sraw;
        int v0 = bid * 512 + tid * 2;
        int b = v0 / VOX, s = v0 % VOX;
        const float* p = inp + (size_t)b * 32 * VOX + s;
        float2 x0 = *(const float2*)p;
        float m0 = -1e30f, m1 = -1e30f;
        #pragma unroll 16
        for (int c = 1; c < 32; c++) {
            float2 y = *(const float2*)&p[c * VOX];
            m0 = fmaxf(m0, y.x);
            m1 = fmaxf(m1, y.y);
        }
        unsigned bits = (m0 > x0.x ? 1u : 0u) | (m1 > x0.y ? 2u : 0u);
        sb[tid] = (unsigned char)bits;
        __syncthreads();
        if (tid < 8) {
            unsigned long long pat = 0;
            #pragma unroll
            for (int i = 0; i < 32; i++)
                pat |= (unsigned long long)sb[tid * 32 + i] << (2 * i);
            g_pat[bid * 8 + tid] = pat;
        }
        if (bid == 0) {
            for (int i = tid; i < K_CODES; i += 256) g_avgp[i] = 0.f;
            if (tid < 8) g_sums[tid] = 0.f;
            if (tid == 0) g_ctr = 0;
        }
    } else if (bid < 560) {
        // ---- norm_z ----
        int nb = bid - 432;
        float* sm = (float*)sraw;
        float* pnormf = sm + 256 * NZ_PAD;              // [8][32]
        float* norm = pnormf + 8 * 32;                  // [NZ_SCH]
        int b = nb >> 3;
        int s0 = (nb & 7) * NZ_SCH;
        const float* src = z_e + (size_t)b * C_DIM * SPAT + s0;
        for (int i = tid; i < 256 * NZ_SCH; i += 256) {
            int c = i / NZ_SCH, s = i - c * NZ_SCH;
            sm[c * NZ_PAD + s] = src[c * SPAT + s];
        }
        __syncthreads();
        int cg = tid >> 5, lane = tid & 31;
        if (lane < NZ_SCH) {
            float acc = 0.f;
            #pragma unroll
            for (int k = 0; k < 32; k++) {
                float v = sm[(cg * 32 + k) * NZ_PAD + lane];
                acc += v * v;
            }
            pnormf[cg * 32 + lane] = acc;
        }
        __syncthreads();
        if (tid < NZ_SCH) {
            float a = 0.f;
            #pragma unroll
            for (int g = 0; g < 8; g++) a += pnormf[g * 32 + tid];
            norm[tid] = fmaxf(sqrtf(a), 1e-12f);
        }
        __syncthreads();
        for (int i = tid; i < 256 * NZ_SCH; i += 256) {
            int s = i >> 8, c = i & 255;
            float vn = sm[c * NZ_PAD + s] / norm[s];
            int n = b * SPAT + s0 + s;
            g_zn[n * C_DIM + c] = vn;
            __nv_bfloat16 b0, b1;
            bsplit2(vn, b0, b1);
            g_z0[n * C_DIM + c] = b0;
            g_z1[n * C_DIM + c] = b1;
        }
    } else {
        // ---- norm_cb ----
        int k = bid - 560;
        float* red = (float*)sraw;
        float v = cb[k * C_DIM + tid];
        float ss = bsum256(v * v, red);
        float vn = v / fmaxf(sqrtf(ss), 1e-12f);
        g_en[k * C_DIM + tid] = vn;
        __nv_bfloat16 b0, b1;
        bsplit2(vn, b0, b1);
        g_e0[k * C_DIM + tid] = b0;
        g_e1[k * C_DIM + tid] = b1;
    }
}

// =======================================================================
// K_MID: affinity (blocks 0..431) | ham triangle (432..1187)  [frozen]
// =======================================================================
#define AF_PAD 40
#define HM_PAD 72
#define MID_BYTES 31232
__global__ __launch_bounds__(256) void k_mid() {
    __shared__ __align__(16) char sraw[MID_BYTES];
    int tid = threadIdx.x;
    int bid = blockIdx.x;
    int warp = tid >> 5, lane = tid & 31;
    int wi = warp >> 2, wj = warp & 3;

    if (bid < 432) {
        __nv_bfloat16* As0 = (__nv_bfloat16*)sraw;
        __nv_bfloat16* As1 = As0 + 64 * AF_PAD;
        __nv_bfloat16* Bs0 = As1 + 64 * AF_PAD;
        __nv_bfloat16* Bs1 = Bs0 + 128 * AF_PAD;
        __nv_bfloat16* Asp[2] = {As0, As1};
        __nv_bfloat16* Bsp[2] = {Bs0, Bs1};

        int rowBase = (bid >> 3) * 64;
        int colBase = (bid & 7) * 128;
        const __nv_bfloat16* Az0 = g_z0 + rowBase * C_DIM;
        const __nv_bfloat16* Az1 = g_z1 + rowBase * C_DIM;
        const __nv_bfloat16* Be0 = g_e0 + colBase * C_DIM;
        const __nv_bfloat16* Be1 = g_e1 + colBase * C_DIM;

        uint32_t sA[2], sB[2];
        sA[0] = (uint32_t)__cvta_generic_to_shared(As0);
        sA[1] = (uint32_t)__cvta_generic_to_shared(As1);
        sB[0] = (uint32_t)__cvta_generic_to_shared(Bs0);
        sB[1] = (uint32_t)__cvta_generic_to_shared(Bs1);

        int aspl[2], arow[2], apart[2];
        int bspl[4], brow[4], bpart[4];
        #pragma unroll
        for (int i = 0; i < 2; i++) {
            int g = tid + i * 256;
            aspl[i] = g >> 8; int idx = g & 255;
            arow[i] = idx >> 2; apart[i] = idx & 3;
        }
        #pragma unroll
        for (int i = 0; i < 4; i++) {
            int h = tid + i * 256;
            bspl[i] = h >> 9; int idx = h & 511;
            brow[i] = idx >> 2; bpart[i] = idx & 3;
        }

        uint4 pf[6];
        auto loadregs = [&](int kc) {
            #pragma unroll
            for (int i = 0; i < 2; i++) {
                const __nv_bfloat16* base = aspl[i] ? Az1 : Az0;
                pf[i] = *(const uint4*)&base[arow[i] * C_DIM + kc + apart[i] * 8];
            }
            #pragma unroll
            for (int i = 0; i < 4; i++) {
                const __nv_bfloat16* base = bspl[i] ? Be1 : Be0;
                pf[2 + i] = *(const uint4*)&base[brow[i] * C_DIM + kc + bpart[i] * 8];
            }
        };
        auto storeregs = [&]() {
            #pragma unroll
            for (int i = 0; i < 2; i++)
                *(uint4*)&Asp[aspl[i]][arow[i] * AF_PAD + apart[i] * 8] = pf[i];
            #pragma unroll
            for (int i = 0; i < 4; i++)
                *(uint4*)&Bsp[bspl[i]][brow[i] * AF_PAD + bpart[i] * 8] = pf[2 + i];
        };

        float acc[2][4][4] = {};
        loadregs(0);
        storeregs();
        __syncthreads();

        for (int c = 0; c < 8; c++) {
            if (c < 7) loadregs((c + 1) * 32);
            #pragma unroll
            for (int ks = 0; ks < 2; ks++) {
                int k0 = ks * 16;
                uint32_t a[2][2][4], b[2][2][4];
                #pragma unroll
                for (int s = 0; s < 2; s++) {
                    #pragma unroll
                    for (int mt = 0; mt < 2; mt++) {
                        int rb = wi * 32 + mt * 16;
                        uint32_t addr = sA[s] + ((rb + (lane & 15)) * AF_PAD + k0 + (lane >> 4) * 8) * 2;
                        ldsm_x4(a[s][mt][0], a[s][mt][1], a[s][mt][2], a[s][mt][3], addr);
                    }
                    #pragma unroll
                    for (int ng = 0; ng < 2; ng++) {
                        int row = wj * 32 + ng * 16 + (lane & 7) + ((lane >> 4) << 3);
                        int koff = k0 + ((lane >> 3) & 1) * 8;
                        uint32_t addr = sB[s] + (row * AF_PAD + koff) * 2;
                        ldsm_x4(b[s][ng][0], b[s][ng][1], b[s][ng][2], b[s][ng][3], addr);
                    }
                }
                #pragma unroll
                for (int mt = 0; mt < 2; mt++)
                    #pragma unroll
                    for (int nt = 0; nt < 4; nt++) {
                        int ng = nt >> 1, off = (nt & 1) * 2;
                        float* cc = acc[mt][nt];
                        mma_bf16(cc, a[0][mt][0], a[0][mt][1], a[0][mt][2], a[0][mt][3],
                                 b[0][ng][off], b[0][ng][off + 1]);
                        mma_bf16(cc, a[0][mt][0], a[0][mt][1], a[0][mt][2], a[0][mt][3],
                                 b[1][ng][off], b[1][ng][off + 1]);
                        mma_bf16(cc, a[1][mt][0], a[1][mt][1], a[1][mt][2], a[1][mt][3],
                                 b[0][ng][off], b[0][ng][off + 1]);
                    }
            }
            __syncthreads();
            if (c < 7) {
                storeregs();
                __syncthreads();
            }
        }

        #pragma unroll
        for (int mt = 0; mt < 2; mt++) {
            #pragma unroll
            for (int nt = 0; nt < 4; nt++) {
                int i0 = rowBase + wi * 32 + mt * 16 + (lane >> 2);
                int j0 = colBase + wj * 32 + nt * 8 + (lane & 3) * 2;
                *(float2*)&g_aff[i0 * K_CODES + j0] = make_float2(acc[mt][nt][0], acc[mt][nt][1]);
                *(float2*)&g_aff[(i0 + 8) * K_CODES + j0] = make_float2(acc[mt][nt][2], acc[mt][nt][3]);
            }
        }
    } else {
        int id = bid - 432;
        int jt = (int)((sqrtf(4.f * id + 1.f) - 1.f) * 0.5f);
        while (jt * jt + jt > id) jt--;
        while ((jt + 1) * (jt + 1) + (jt + 1) <= id) jt++;
        int it = id - (jt * jt + jt);

        __nv_bfloat16* Ahs = (__nv_bfloat16*)sraw;
        __nv_bfloat16* Bhs = Ahs + 64 * HM_PAD;
        unsigned long long* spi = (unsigned long long*)(Bhs + 128 * HM_PAD);
        unsigned long long* spj = spi + 64;
        float* red = (float*)(spj + 128);

        const __nv_bfloat16* Ag = g_z0 + it * 64 * C_DIM;
        const __nv_bfloat16* Bg = g_z0 + jt * 128 * C_DIM;
        if (tid < 64)        spi[tid] = g_pat[it * 64 + tid];
        else if (tid < 192)  spj[tid - 64] = g_pat[jt * 128 + tid - 64];

        uint32_t sA = (uint32_t)__cvta_generic_to_shared(Ahs);
        uint32_t sB = (uint32_t)__cvta_generic_to_shared(Bhs);
        float acc[2][4][4] = {};

        for (int kc = 0; kc < C_DIM; kc += 64) {
            __syncthreads();
            #pragma unroll
            for (int i = 0; i < 6; i++) {
                int g = tid + i * 256;
                if (g < 512) {
                    int row = g >> 3, part = g & 7;
                    *(uint4*)&Ahs[row * HM_PAD + part * 8] = *(const uint4*)&Ag[row * C_DIM + kc + part * 8];
                } else {
                    int h = g - 512;
                    int row = h >> 3, part = h & 7;
                    *(uint4*)&Bhs[row * HM_PAD + part * 8] = *(const uint4*)&Bg[row * C_DIM + kc + part * 8];
                }
            }
            __syncthreads();
            #pragma unroll
            for (int ks = 0; ks < 4; ks++) {
                int k0 = ks * 16;
                uint32_t a[2][4], b[2][4];
                #pragma unroll
                for (int mt = 0; mt < 2; mt++) {
                    int rb = wi * 32 + mt * 16;
                    uint32_t addr = sA + ((rb + (lane & 15)) * HM_PAD + k0 + (lane >> 4) * 8) * 2;
                    ldsm_x4(a[mt][0], a[mt][1], a[mt][2], a[mt][3], addr);
                }
                #pragma unroll
                for (int ng = 0; ng < 2; ng++) {
                    int row = wj * 32 + ng * 16 + (lane & 7) + ((lane >> 4) << 3);
                    int koff = k0 + ((lane >> 3) & 1) * 8;
                    uint32_t addr = sB + (row * HM_PAD + koff) * 2;
                    ldsm_x4(b[ng][0], b[ng][1], b[ng][2], b[ng][3], addr);
                }
                #pragma unroll
                for (int mt = 0; mt < 2; mt++)
                    #pragma unroll
                    for (int nt = 0; nt < 4; nt++) {
                        int ng = nt >> 1, off = (nt & 1) * 2;
                        mma_bf16(acc[mt][nt], a[mt][0], a[mt][1], a[mt][2], a[mt][3],
                                 b[ng][off], b[ng][off + 1]);
                    }
            }
        }

        float ws = 0.f, wc = 0.f;
        #pragma unroll
        for (int mt = 0; mt < 2; mt++) {
            #pragma unroll
            for (int nt = 0; nt < 4; nt++) {
                int li0 = wi * 32 + mt * 16 + (lane >> 2);
                int lj0 = wj * 32 + nt * 8 + (lane & 3) * 2;
                #pragma unroll
                for (int hh = 0; hh < 2; hh++) {
                    int li = li0 + hh * 8;
                    int gi = it * 64 + li;
                    unsigned long long pi = spi[li];
                    #pragma unroll
                    for (int jj = 0; jj < 2; jj++) {
                        int lj = lj0 + jj;
                        int gj = jt * 128 + lj;
                        int h = __popcll(pi ^ spj[lj]);
                        if (gj > gi && h <= 5) {
                            float w = 1.0f - (float)h * (1.0f / 64.0f);
                            ws += w;
                            wc += w * acc[mt][nt][hh * 2 + jj];
                        }
                    }
                }
            }
        }
        float wsb = bsum256(ws * 2.0f, red);
        float wcb = bsum256(wc * 2.0f, red);
        if (tid == 0) {
            atomicAdd(&g_sums[2], wsb);
            atomicAdd(&g_sums[3], wcb);
        }
    }
}

// =======================================================================
// K_POST: per-row pass, warp-local softmax (2 syncs/row) + last-block final
// =======================================================================
#define ROWS_PB 8
__global__ __launch_bounds__(256) void k_post(float* __restrict__ out) {
    int n0 = blockIdx.x * ROWS_PB, t = threadIdx.x;
    int lane = t & 31, wid = t >> 5;
    __shared__ float swm[8], sws[8], swt[8];
    __shared__ int   swi[8];
    __shared__ float redA[8];
    __shared__ float zqs[ROWS_PB][C_DIM + 1];
    __shared__ int slast;

    float avg_acc[4] = {0.f, 0.f, 0.f, 0.f};
    float ent_acc = 0.f, sse_local = 0.f;

    for (int rr = 0; rr < ROWS_PB; rr++) {
        int n = n0 + rr;
        float fa[4];
        #pragma unroll
        for (int q = 0; q < 4; q++)
            fa[q] = g_aff[n * K_CODES + t + q * 256] * 100.0f;

        // warp max + argmax (first-occurrence tiebreak)
        float m = fa[0]; int mi = t;
        #pragma unroll
        for (int q = 1; q < 4; q++)
            if (fa[q] > m) { m = fa[q]; mi = t + q * 256; }
        #pragma unroll
        for (int o = 16; o; o >>= 1) {
            float om = __shfl_xor_sync(0xffffffffu, m, o);
            int   oi = __shfl_xor_sync(0xffffffffu, mi, o);
            if (om > m || (om == m && oi < mi)) { m = om; mi = oi; }
        }
        // warp-local softmax stats (relative warp max m)
        float e[4], se = 0.f, te = 0.f;
        #pragma unroll
        for (int q = 0; q < 4; q++) {
            float d = fa[q] - m;
            e[q] = fexp(d);
            se += e[q];
            te += e[q] * d;
        }
        #pragma unroll
        for (int o = 16; o; o >>= 1) {
            se += __shfl_xor_sync(0xffffffffu, se, o);
            te += __shfl_xor_sync(0xffffffffu, te, o);
        }
        if (lane == 0) { swm[wid] = m; swi[wid] = mi; sws[wid] = se; swt[wid] = te; }
        __syncthreads();

        // combine 8 warps (all threads identically)
        float bm = swm[0]; int bidx = swi[0];
        #pragma unroll
        for (int w = 1; w < 8; w++)
            if (swm[w] > bm || (swm[w] == bm && swi[w] < bidx)) { bm = swm[w]; bidx = swi[w]; }
        float Z = 0.f, T = 0.f;
        #pragma unroll
        for (int w = 0; w < 8; w++) {
            float f = fexp(swm[w] - bm);
            Z += sws[w] * f;
            T += f * (swt[w] + (swm[w] - bm) * sws[w]);
        }
        float fown = fexp(m - bm);
        float invZ = 1.0f / Z;
        #pragma unroll
        for (int q = 0; q < 4; q++) avg_acc[q] += e[q] * fown * invZ;

        if (t == 0) {
            ent_acc += logf(Z) - T / Z;
            out[OUT_IDX + n] = (float)bidx;
        }
        float zq = g_en[bidx * C_DIM + t];
        float zn = g_zn[n * C_DIM + t];
        zqs[rr][t] = zq;
        float dd = zq - zn;
        sse_local += dd * dd;
        __syncthreads();   // protect swm/sws/swt/swi for next row
    }

    // single block-wide SSE reduction
    float sse = bsum256(sse_local, redA);

    // coalesced z_q write
    {
        int b = n0 / SPAT, s0 = n0 % SPAT;
        float* dst = out + ((size_t)b * C_DIM) * SPAT + s0;
        for (int i = t; i < C_DIM * ROWS_PB; i += 256) {
            int c = i >> 3, rr = i & 7;
            dst[c * SPAT + rr] = zqs[rr][c];
        }
    }

    const float invN = 1.0f / (float)N_ROWS;
    #pragma unroll
    for (int q = 0; q < 4; q++)
        atomicAdd(&g_avgp[t + q * 256], avg_acc[q] * invN);
    if (t == 0) {
        atomicAdd(&g_sums[1], ent_acc);
        atomicAdd(&g_sums[0], sse);
    }

    // ---- last block performs final combine ----
    __threadfence();
    if (t == 0) {
        int old = atomicAdd(&g_ctr, 1);
        slast = (old == (int)gridDim.x - 1) ? 1 : 0;
    }
    __syncthreads();
    if (slast) {
        __threadfence();
        float v = 0.f;
        #pragma unroll
        for (int q = 0; q < 4; q++) {
            float p = g_avgp[t + q * 256];
            v += p * logf(p + 1e-5f);
        }
        float s = bsum256(v, redA);
        if (t == 0) {
            float sseT = g_sums[0];
            float sent = g_sums[1];
            float sw   = g_sums[2];
            float swc  = g_sums[3];
            float codebook_loss = sseT / (float)(N_ROWS * C_DIM);
            float commit_loss   = 0.25f * codebook_loss;
            float sample_entropy = sent / (float)N_ROWS;
            float avg_entropy    = -s;
            float ent_loss = 0.1f * (sample_entropy - avg_entropy);
            float ham_loss = (sw - swc) / (sw + 1e-8f);
            out[OUT_LOSS] = codebook_loss + commit_loss + ent_loss + ham_loss;
        }
    }
}

// ---------------- launch ----------------
extern "C" void kernel_launch(void* const* d_in, const int* in_sizes, int n_in,
                              void* d_out, int out_size) {
    const float* input_blocks = (const float*)d_in[0];
    const float* z_e          = (const float*)d_in[1];
    const float* codebook     = (const float*)d_in[2];
    float* out = (float*)d_out;

    k_pre<<<1584, 256>>>(input_blocks, z_e, codebook);
    k_mid<<<1188, 256>>>();
    k_post<<<N_ROWS / ROWS_PB, 256>>>(out);
}

// round 12
// speedup vs baseline: 1.0162x; 1.0162x over previous
#include <cuda_runtime.h>
#include <cuda_bf16.h>
#include <math.h>
#include <stdint.h>

#define N_ROWS 3456      // 16 * 216
#define C_DIM  256
#define K_CODES 1024
#define B_SZ   16
#define SPAT   216       // 6*6*6
#define VOX    13824     // 24^3
#define OUT_ZQ (B_SZ * C_DIM * SPAT)   // 884736
#define OUT_LOSS OUT_ZQ
#define OUT_IDX (OUT_ZQ + 1)

// ---------------- device scratch ----------------
__device__ float g_zn[N_ROWS * C_DIM];
__device__ __nv_bfloat16 g_z0[N_ROWS * C_DIM];
__device__ __nv_bfloat16 g_z1[N_ROWS * C_DIM];
__device__ float g_en[K_CODES * C_DIM];
__device__ __nv_bfloat16 g_e0[K_CODES * C_DIM];
__device__ __nv_bfloat16 g_e1[K_CODES * C_DIM];
__device__ float g_aff[N_ROWS * K_CODES];
__device__ unsigned long long g_pat[N_ROWS];
__device__ float g_avgp[K_CODES];
__device__ float g_sums[8];   // 0: SSE, 1: entropy sum, 2: sumW, 3: sumWcos
__device__ int g_ctr;

// ---------------- helpers ----------------
__device__ __forceinline__ float bsum256(float v, float* red) {
    #pragma unroll
    for (int o = 16; o; o >>= 1) v += __shfl_xor_sync(0xffffffffu, v, o);
    __syncthreads();
    if ((threadIdx.x & 31) == 0) red[threadIdx.x >> 5] = v;
    __syncthreads();
    float s = 0.f;
    #pragma unroll
    for (int w = 0; w < 8; w++) s += red[w];
    return s;
}

__device__ __forceinline__ float fexp(float d) {   // e^d for d <= 0
    float r;
    asm("ex2.approx.f32 %0, %1;" : "=f"(r) : "f"(d * 1.4426950408889634f));
    return r;
}

__device__ __forceinline__ void ldsm_x4(uint32_t& r0, uint32_t& r1, uint32_t& r2, uint32_t& r3, uint32_t addr) {
    asm volatile("ldmatrix.sync.aligned.m8n8.x4.shared.b16 {%0,%1,%2,%3}, [%4];"
                 : "=r"(r0), "=r"(r1), "=r"(r2), "=r"(r3) : "r"(addr));
}
__device__ __forceinline__ void mma_bf16(float* c, uint32_t a0, uint32_t a1, uint32_t a2, uint32_t a3,
                                         uint32_t b0, uint32_t b1) {
    asm volatile("mma.sync.aligned.m16n8k16.row.col.f32.bf16.bf16.f32 "
                 "{%0,%1,%2,%3}, {%4,%5,%6,%7}, {%8,%9}, {%0,%1,%2,%3};"
                 : "+f"(c[0]), "+f"(c[1]), "+f"(c[2]), "+f"(c[3])
                 : "r"(a0), "r"(a1), "r"(a2), "r"(a3), "r"(b0), "r"(b1));
}

__device__ __forceinline__ void bsplit2(float x, __nv_bfloat16& b0, __nv_bfloat16& b1) {
    b0 = __float2bfloat16_rn(x);
    b1 = __float2bfloat16_rn(x - __bfloat162float(b0));
}

// =======================================================================
// K_PRE: pattern (blocks 0..215) | norm_z (216..343) | norm_cb (344..1367)
// (pattern branch = R10-exact: 4 vox/thread, 16 patterns/block)
// =======================================================================
#define NZ_SCH 27
#define NZ_PAD 29
#define PRE_NZ_BYTES (256 * NZ_PAD * 4 + 8 * 32 * 4 + NZ_SCH * 4 + 64)
__global__ __launch_bounds__(256) void k_pre(const float* __restrict__ inp,
                                             const float* __restrict__ z_e,
                                             const float* __restrict__ cb) {
    __shared__ __align__(16) char sraw[PRE_NZ_BYTES];
    int tid = threadIdx.x;
    int bid = blockIdx.x;

    if (bid < 216) {
        // ---- patterns: 4 voxels/thread, 16 patterns/block ----
        unsigned char* sb = (unsigned char*)sraw;
        int v0 = (bid * 256 + tid) * 4;
        int b = v0 / VOX, s = v0 % VOX;
        const float* p = inp + (size_t)b * 32 * VOX + s;
        float4 x0 = *(const float4*)p;
        float m0 = -1e30f, m1 = -1e30f, m2 = -1e30f, m3 = -1e30f;
        #pragma unroll 4
        for (int c = 1; c < 32; c++) {
            float4 y = *(const float4*)&p[c * VOX];
            m0 = fmaxf(m0, y.x);
            m1 = fmaxf(m1, y.y);
            m2 = fmaxf(m2, y.z);
            m3 = fmaxf(m3, y.w);
        }
        unsigned bits = (m0 > x0.x ? 1u : 0u) | (m1 > x0.y ? 2u : 0u) |
                        (m2 > x0.z ? 4u : 0u) | (m3 > x0.w ? 8u : 0u);
        sb[tid] = (unsigned char)bits;
        __syncthreads();
        if (tid < 16) {
            unsigned long long pat = 0;
            #pragma unroll
            for (int i = 0; i < 16; i++)
                pat |= (unsigned long long)sb[tid * 16 + i] << (4 * i);
            g_pat[bid * 16 + tid] = pat;
        }
        if (bid == 0) {
            for (int i = tid; i < K_CODES; i += 256) g_avgp[i] = 0.f;
            if (tid < 8) g_sums[tid] = 0.f;
            if (tid == 0) g_ctr = 0;
        }
    } else if (bid < 344) {
        // ---- norm_z ----
        int nb = bid - 216;
        float* sm = (float*)sraw;
        float* pnormf = sm + 256 * NZ_PAD;              // [8][32]
        float* norm = pnormf + 8 * 32;                  // [NZ_SCH]
        int b = nb >> 3;
        int s0 = (nb & 7) * NZ_SCH;
        const float* src = z_e + (size_t)b * C_DIM * SPAT + s0;
        for (int i = tid; i < 256 * NZ_SCH; i += 256) {
            int c = i / NZ_SCH, s = i - c * NZ_SCH;
            sm[c * NZ_PAD + s] = src[c * SPAT + s];
        }
        __syncthreads();
        int cg = tid >> 5, lane = tid & 31;
        if (lane < NZ_SCH) {
            float acc = 0.f;
            #pragma unroll
            for (int k = 0; k < 32; k++) {
                float v = sm[(cg * 32 + k) * NZ_PAD + lane];
                acc += v * v;
            }
            pnormf[cg * 32 + lane] = acc;
        }
        __syncthreads();
        if (tid < NZ_SCH) {
            float a = 0.f;
            #pragma unroll
            for (int g = 0; g < 8; g++) a += pnormf[g * 32 + tid];
            norm[tid] = fmaxf(sqrtf(a), 1e-12f);
        }
        __syncthreads();
        for (int i = tid; i < 256 * NZ_SCH; i += 256) {
            int s = i >> 8, c = i & 255;
            float vn = sm[c * NZ_PAD + s] / norm[s];
            int n = b * SPAT + s0 + s;
            g_zn[n * C_DIM + c] = vn;
            __nv_bfloat16 b0, b1;
            bsplit2(vn, b0, b1);
            g_z0[n * C_DIM + c] = b0;
            g_z1[n * C_DIM + c] = b1;
        }
    } else {
        // ---- norm_cb ----
        int k = bid - 344;
        float* red = (float*)sraw;
        float v = cb[k * C_DIM + tid];
        float ss = bsum256(v * v, red);
        float vn = v / fmaxf(sqrtf(ss), 1e-12f);
        g_en[k * C_DIM + tid] = vn;
        __nv_bfloat16 b0, b1;
        bsplit2(vn, b0, b1);
        g_e0[k * C_DIM + tid] = b0;
        g_e1[k * C_DIM + tid] = b1;
    }
}

// =======================================================================
// K_MID: affinity (blocks 0..431) | ham triangle (432..1187)  [frozen]
// =======================================================================
#define AF_PAD 40
#define HM_PAD 72
#define MID_BYTES 31232
__global__ __launch_bounds__(256) void k_mid() {
    __shared__ __align__(16) char sraw[MID_BYTES];
    int tid = threadIdx.x;
    int bid = blockIdx.x;
    int warp = tid >> 5, lane = tid & 31;
    int wi = warp >> 2, wj = warp & 3;

    if (bid < 432) {
        __nv_bfloat16* As0 = (__nv_bfloat16*)sraw;
        __nv_bfloat16* As1 = As0 + 64 * AF_PAD;
        __nv_bfloat16* Bs0 = As1 + 64 * AF_PAD;
        __nv_bfloat16* Bs1 = Bs0 + 128 * AF_PAD;
        __nv_bfloat16* Asp[2] = {As0, As1};
        __nv_bfloat16* Bsp[2] = {Bs0, Bs1};

        int rowBase = (bid >> 3) * 64;
        int colBase = (bid & 7) * 128;
        const __nv_bfloat16* Az0 = g_z0 + rowBase * C_DIM;
        const __nv_bfloat16* Az1 = g_z1 + rowBase * C_DIM;
        const __nv_bfloat16* Be0 = g_e0 + colBase * C_DIM;
        const __nv_bfloat16* Be1 = g_e1 + colBase * C_DIM;

        uint32_t sA[2], sB[2];
        sA[0] = (uint32_t)__cvta_generic_to_shared(As0);
        sA[1] = (uint32_t)__cvta_generic_to_shared(As1);
        sB[0] = (uint32_t)__cvta_generic_to_shared(Bs0);
        sB[1] = (uint32_t)__cvta_generic_to_shared(Bs1);

        int aspl[2], arow[2], apart[2];
        int bspl[4], brow[4], bpart[4];
        #pragma unroll
        for (int i = 0; i < 2; i++) {
            int g = tid + i * 256;
            aspl[i] = g >> 8; int idx = g & 255;
            arow[i] = idx >> 2; apart[i] = idx & 3;
        }
        #pragma unroll
        for (int i = 0; i < 4; i++) {
            int h = tid + i * 256;
            bspl[i] = h >> 9; int idx = h & 511;
            brow[i] = idx >> 2; bpart[i] = idx & 3;
        }

        uint4 pf[6];
        auto loadregs = [&](int kc) {
            #pragma unroll
            for (int i = 0; i < 2; i++) {
                const __nv_bfloat16* base = aspl[i] ? Az1 : Az0;
                pf[i] = *(const uint4*)&base[arow[i] * C_DIM + kc + apart[i] * 8];
            }
            #pragma unroll
            for (int i = 0; i < 4; i++) {
                const __nv_bfloat16* base = bspl[i] ? Be1 : Be0;
                pf[2 + i] = *(const uint4*)&base[brow[i] * C_DIM + kc + bpart[i] * 8];
            }
        };
        auto storeregs = [&]() {
            #pragma unroll
            for (int i = 0; i < 2; i++)
                *(uint4*)&Asp[aspl[i]][arow[i] * AF_PAD + apart[i] * 8] = pf[i];
            #pragma unroll
            for (int i = 0; i < 4; i++)
                *(uint4*)&Bsp[bspl[i]][brow[i] * AF_PAD + bpart[i] * 8] = pf[2 + i];
        };

        float acc[2][4][4] = {};
        loadregs(0);
        storeregs();
        __syncthreads();

        for (int c = 0; c < 8; c++) {
            if (c < 7) loadregs((c + 1) * 32);
            #pragma unroll
            for (int ks = 0; ks < 2; ks++) {
                int k0 = ks * 16;
                uint32_t a[2][2][4], b[2][2][4];
                #pragma unroll
                for (int s = 0; s < 2; s++) {
                    #pragma unroll
                    for (int mt = 0; mt < 2; mt++) {
                        int rb = wi * 32 + mt * 16;
                        uint32_t addr = sA[s] + ((rb + (lane & 15)) * AF_PAD + k0 + (lane >> 4) * 8) * 2;
                        ldsm_x4(a[s][mt][0], a[s][mt][1], a[s][mt][2], a[s][mt][3], addr);
                    }
                    #pragma unroll
                    for (int ng = 0; ng < 2; ng++) {
                        int row = wj * 32 + ng * 16 + (lane & 7) + ((lane >> 4) << 3);
                        int koff = k0 + ((lane >> 3) & 1) * 8;
                        uint32_t addr = sB[s] + (row * AF_PAD + koff) * 2;
                        ldsm_x4(b[s][ng][0], b[s][ng][1], b[s][ng][2], b[s][ng][3], addr);
                    }
                }
                #pragma unroll
                for (int mt = 0; mt < 2; mt++)
                    #pragma unroll
                    for (int nt = 0; nt < 4; nt++) {
                        int ng = nt >> 1, off = (nt & 1) * 2;
                        float* cc = acc[mt][nt];
                        mma_bf16(cc, a[0][mt][0], a[0][mt][1], a[0][mt][2], a[0][mt][3],
                                 b[0][ng][off], b[0][ng][off + 1]);
                        mma_bf16(cc, a[0][mt][0], a[0][mt][1], a[0][mt][2], a[0][mt][3],
                                 b[1][ng][off], b[1][ng][off + 1]);
                        mma_bf16(cc, a[1][mt][0], a[1][mt][1], a[1][mt][2], a[1][mt][3],
                                 b[0][ng][off], b[0][ng][off + 1]);
                    }
            }
            __syncthreads();
            if (c < 7) {
                storeregs();
                __syncthreads();
            }
        }

        #pragma unroll
        for (int mt = 0; mt < 2; mt++) {
            #pragma unroll
            for (int nt = 0; nt < 4; nt++) {
                int i0 = rowBase + wi * 32 + mt * 16 + (lane >> 2);
                int j0 = colBase + wj * 32 + nt * 8 + (lane & 3) * 2;
                *(float2*)&g_aff[i0 * K_CODES + j0] = make_float2(acc[mt][nt][0], acc[mt][nt][1]);
                *(float2*)&g_aff[(i0 + 8) * K_CODES + j0] = make_float2(acc[mt][nt][2], acc[mt][nt][3]);
            }
        }
    } else {
        int id = bid - 432;
        int jt = (int)((sqrtf(4.f * id + 1.f) - 1.f) * 0.5f);
        while (jt * jt + jt > id) jt--;
        while ((jt + 1) * (jt + 1) + (jt + 1) <= id) jt++;
        int it = id - (jt * jt + jt);

        __nv_bfloat16* Ahs = (__nv_bfloat16*)sraw;
        __nv_bfloat16* Bhs = Ahs + 64 * HM_PAD;
        unsigned long long* spi = (unsigned long long*)(Bhs + 128 * HM_PAD);
        unsigned long long* spj = spi + 64;
        float* red = (float*)(spj + 128);

        const __nv_bfloat16* Ag = g_z0 + it * 64 * C_DIM;
        const __nv_bfloat16* Bg = g_z0 + jt * 128 * C_DIM;
        if (tid < 64)        spi[tid] = g_pat[it * 64 + tid];
        else if (tid < 192)  spj[tid - 64] = g_pat[jt * 128 + tid - 64];

        uint32_t sA = (uint32_t)__cvta_generic_to_shared(Ahs);
        uint32_t sB = (uint32_t)__cvta_generic_to_shared(Bhs);
        float acc[2][4][4] = {};

        for (int kc = 0; kc < C_DIM; kc += 64) {
            __syncthreads();
            #pragma unroll
            for (int i = 0; i < 6; i++) {
                int g = tid + i * 256;
                if (g < 512) {
                    int row = g >> 3, part = g & 7;
                    *(uint4*)&Ahs[row * HM_PAD + part * 8] = *(const uint4*)&Ag[row * C_DIM + kc + part * 8];
                } else {
                    int h = g - 512;
                    int row = h >> 3, part = h & 7;
                    *(uint4*)&Bhs[row * HM_PAD + part * 8] = *(const uint4*)&Bg[row * C_DIM + kc + part * 8];
                }
            }
            __syncthreads();
            #pragma unroll
            for (int ks = 0; ks < 4; ks++) {
                int k0 = ks * 16;
                uint32_t a[2][4], b[2][4];
                #pragma unroll
                for (int mt = 0; mt < 2; mt++) {
                    int rb = wi * 32 + mt * 16;
                    uint32_t addr = sA + ((rb + (lane & 15)) * HM_PAD + k0 + (lane >> 4) * 8) * 2;
                    ldsm_x4(a[mt][0], a[mt][1], a[mt][2], a[mt][3], addr);
                }
                #pragma unroll
                for (int ng = 0; ng < 2; ng++) {
                    int row = wj * 32 + ng * 16 + (lane & 7) + ((lane >> 4) << 3);
                    int koff = k0 + ((lane >> 3) & 1) * 8;
                    uint32_t addr = sB + (row * HM_PAD + koff) * 2;
                    ldsm_x4(b[ng][0], b[ng][1], b[ng][2], b[ng][3], addr);
                }
                #pragma unroll
                for (int mt = 0; mt < 2; mt++)
                    #pragma unroll
                    for (int nt = 0; nt < 4; nt++) {
                        int ng = nt >> 1, off = (nt & 1) * 2;
                        mma_bf16(acc[mt][nt], a[mt][0], a[mt][1], a[mt][2], a[mt][3],
                                 b[ng][off], b[ng][off + 1]);
                    }
            }
        }

        float ws = 0.f, wc = 0.f;
        #pragma unroll
        for (int mt = 0; mt < 2; mt++) {
            #pragma unroll
            for (int nt = 0; nt < 4; nt++) {
                int li0 = wi * 32 + mt * 16 + (lane >> 2);
                int lj0 = wj * 32 + nt * 8 + (lane & 3) * 2;
                #pragma unroll
                for (int hh = 0; hh < 2; hh++) {
                    int li = li0 + hh * 8;
                    int gi = it * 64 + li;
                    unsigned long long pi = spi[li];
                    #pragma unroll
                    for (int jj = 0; jj < 2; jj++) {
                        int lj = lj0 + jj;
                        int gj = jt * 128 + lj;
                        int h = __popcll(pi ^ spj[lj]);
                        if (gj > gi && h <= 5) {
                            float w = 1.0f - (float)h * (1.0f / 64.0f);
                            ws += w;
                            wc += w * acc[mt][nt][hh * 2 + jj];
                        }
                    }
                }
            }
        }
        float wsb = bsum256(ws * 2.0f, red);
        float wcb = bsum256(wc * 2.0f, red);
        if (tid == 0) {
            atomicAdd(&g_sums[2], wsb);
            atomicAdd(&g_sums[3], wcb);
        }
    }
}

// =======================================================================
// K_POST: per-row pass, warp-local softmax (2 syncs/row) + last-block final
// =======================================================================
#define ROWS_PB 8
__global__ __launch_bounds__(256) void k_post(float* __restrict__ out) {
    int n0 = blockIdx.x * ROWS_PB, t = threadIdx.x;
    int lane = t & 31, wid = t >> 5;
    __shared__ float swm[8], sws[8], swt[8];
    __shared__ int   swi[8];
    __shared__ float redA[8];
    __shared__ float zqs[ROWS_PB][C_DIM + 1];
    __shared__ int slast;

    float avg_acc[4] = {0.f, 0.f, 0.f, 0.f};
    float ent_acc = 0.f, sse_local = 0.f;

    for (int rr = 0; rr < ROWS_PB; rr++) {
        int n = n0 + rr;
        float fa[4];
        #pragma unroll
        for (int q = 0; q < 4; q++)
            fa[q] = g_aff[n * K_CODES + t + q * 256] * 100.0f;

        // warp max + argmax (first-occurrence tiebreak)
        float m = fa[0]; int mi = t;
        #pragma unroll
        for (int q = 1; q < 4; q++)
            if (fa[q] > m) { m = fa[q]; mi = t + q * 256; }
        #pragma unroll
        for (int o = 16; o; o >>= 1) {
            float om = __shfl_xor_sync(0xffffffffu, m, o);
            int   oi = __shfl_xor_sync(0xffffffffu, mi, o);
            if (om > m || (om == m && oi < mi)) { m = om; mi = oi; }
        }
        // warp-local softmax stats (relative warp max m)
        float e[4], se = 0.f, te = 0.f;
        #pragma unroll
        for (int q = 0; q < 4; q++) {
            float d = fa[q] - m;
            e[q] = fexp(d);
            se += e[q];
            te += e[q] * d;
        }
        #pragma unroll
        for (int o = 16; o; o >>= 1) {
            se += __shfl_xor_sync(0xffffffffu, se, o);
            te += __shfl_xor_sync(0xffffffffu, te, o);
        }
        if (lane == 0) { swm[wid] = m; swi[wid] = mi; sws[wid] = se; swt[wid] = te; }
        __syncthreads();

        // combine 8 warps (all threads identically)
        float bm = swm[0]; int bidx = swi[0];
        #pragma unroll
        for (int w = 1; w < 8; w++)
            if (swm[w] > bm || (swm[w] == bm && swi[w] < bidx)) { bm = swm[w]; bidx = swi[w]; }
        float Z = 0.f, T = 0.f;
        #pragma unroll
        for (int w = 0; w < 8; w++) {
            float f = fexp(swm[w] - bm);
            Z += sws[w] * f;
            T += f * (swt[w] + (swm[w] - bm) * sws[w]);
        }
        float fown = fexp(m - bm);
        float invZ = 1.0f / Z;
        #pragma unroll
        for (int q = 0; q < 4; q++) avg_acc[q] += e[q] * fown * invZ;

        if (t == 0) {
            ent_acc += logf(Z) - T / Z;
            out[OUT_IDX + n] = (float)bidx;
        }
        float zq = g_en[bidx * C_DIM + t];
        float zn = g_zn[n * C_DIM + t];
        zqs[rr][t] = zq;
        float dd = zq - zn;
        sse_local += dd * dd;
        __syncthreads();   // protect swm/sws/swt/swi for next row
    }

    // single block-wide SSE reduction
    float sse = bsum256(sse_local, redA);

    // coalesced z_q write
    {
        int b = n0 / SPAT, s0 = n0 % SPAT;
        float* dst = out + ((size_t)b * C_DIM) * SPAT + s0;
        for (int i = t; i < C_DIM * ROWS_PB; i += 256) {
            int c = i >> 3, rr = i & 7;
            dst[c * SPAT + rr] = zqs[rr][c];
        }
    }

    const float invN = 1.0f / (float)N_ROWS;
    #pragma unroll
    for (int q = 0; q < 4; q++)
        atomicAdd(&g_avgp[t + q * 256], avg_acc[q] * invN);
    if (t == 0) {
        atomicAdd(&g_sums[1], ent_acc);
        atomicAdd(&g_sums[0], sse);
    }

    // ---- last block performs final combine ----
    __threadfence();
    if (t == 0) {
        int old = atomicAdd(&g_ctr, 1);
        slast = (old == (int)gridDim.x - 1) ? 1 : 0;
    }
    __syncthreads();
    if (slast) {
        __threadfence();
        float v = 0.f;
        #pragma unroll
        for (int q = 0; q < 4; q++) {
            float p = g_avgp[t + q * 256];
            v += p * logf(p + 1e-5f);
        }
        float s = bsum256(v, redA);
        if (t == 0) {
            float sseT = g_sums[0];
            float sent = g_sums[1];
            float sw   = g_sums[2];
            float swc  = g_sums[3];
            float codebook_loss = sseT / (float)(N_ROWS * C_DIM);
            float commit_loss   = 0.25f * codebook_loss;
            float sample_entropy = sent / (float)N_ROWS;
            float avg_entropy    = -s;
            float ent_loss = 0.1f * (sample_entropy - avg_entropy);
            float ham_loss = (sw - swc) / (sw + 1e-8f);
            out[OUT_LOSS] = codebook_loss + commit_loss + ent_loss + ham_loss;
        }
    }
}

// ---------------- launch ----------------
extern "C" void kernel_launch(void* const* d_in, const int* in_sizes, int n_in,
                              void* d_out, int out_size) {
    const float* input_blocks = (const float*)d_in[0];
    const float* z_e          = (const float*)d_in[1];
    const float* codebook     = (const float*)d_in[2];
    float* out = (float*)d_out;

    k_pre<<<1368, 256>>>(input_blocks, z_e, codebook);
    k_mid<<<1188, 256>>>();
    k_post<<<N_ROWS / ROWS_PB, 256>>>(out);
}

// round 13
// speedup vs baseline: 1.0617x; 1.0448x over previous
#include <cuda_runtime.h>
#include <cuda_bf16.h>
#include <math.h>
#include <stdint.h>

#define N_ROWS 3456      // 16 * 216
#define C_DIM  256
#define K_CODES 1024
#define B_SZ   16
#define SPAT   216       // 6*6*6
#define VOX    13824     // 24^3
#define OUT_ZQ (B_SZ * C_DIM * SPAT)   // 884736
#define OUT_LOSS OUT_ZQ
#define OUT_IDX (OUT_ZQ + 1)

// ---------------- device scratch ----------------
__device__ float g_zn[N_ROWS * C_DIM];
__device__ __nv_bfloat16 g_z0[N_ROWS * C_DIM];
__device__ __nv_bfloat16 g_z1[N_ROWS * C_DIM];
__device__ float g_en[K_CODES * C_DIM];
__device__ __nv_bfloat16 g_e0[K_CODES * C_DIM];
__device__ __nv_bfloat16 g_e1[K_CODES * C_DIM];
__device__ float g_aff[N_ROWS * K_CODES];
__device__ unsigned long long g_pat[N_ROWS];
__device__ float g_avgp[K_CODES];
__device__ float g_sums[8];   // 0: SSE, 1: entropy sum, 2: sumW, 3: sumWcos
__device__ int g_ctr;

// ---------------- helpers ----------------
__device__ __forceinline__ float bsum256(float v, float* red) {
    #pragma unroll
    for (int o = 16; o; o >>= 1) v += __shfl_xor_sync(0xffffffffu, v, o);
    __syncthreads();
    if ((threadIdx.x & 31) == 0) red[threadIdx.x >> 5] = v;
    __syncthreads();
    float s = 0.f;
    #pragma unroll
    for (int w = 0; w < 8; w++) s += red[w];
    return s;
}

__device__ __forceinline__ float fexp(float d) {   // e^d for d <= 0
    float r;
    asm("ex2.approx.f32 %0, %1;" : "=f"(r) : "f"(d * 1.4426950408889634f));
    return r;
}

__device__ __forceinline__ void ldsm_x4(uint32_t& r0, uint32_t& r1, uint32_t& r2, uint32_t& r3, uint32_t addr) {
    asm volatile("ldmatrix.sync.aligned.m8n8.x4.shared.b16 {%0,%1,%2,%3}, [%4];"
                 : "=r"(r0), "=r"(r1), "=r"(r2), "=r"(r3) : "r"(addr));
}
__device__ __forceinline__ void mma_bf16(float* c, uint32_t a0, uint32_t a1, uint32_t a2, uint32_t a3,
                                         uint32_t b0, uint32_t b1) {
    asm volatile("mma.sync.aligned.m16n8k16.row.col.f32.bf16.bf16.f32 "
                 "{%0,%1,%2,%3}, {%4,%5,%6,%7}, {%8,%9}, {%0,%1,%2,%3};"
                 : "+f"(c[0]), "+f"(c[1]), "+f"(c[2]), "+f"(c[3])
                 : "r"(a0), "r"(a1), "r"(a2), "r"(a3), "r"(b0), "r"(b1));
}

__device__ __forceinline__ void bsplit2(float x, __nv_bfloat16& b0, __nv_bfloat16& b1) {
    b0 = __float2bfloat16_rn(x);
    b1 = __float2bfloat16_rn(x - __bfloat162float(b0));
}

// =======================================================================
// K_PRE: pattern (blocks 0..215) | norm_z (216..343) | norm_cb (344..1367)
// =======================================================================
#define NZ_SCH 27
#define NZ_PAD 29
#define PRE_NZ_BYTES (256 * NZ_PAD * 4 + 8 * 32 * 4 + NZ_SCH * 4 + 64)
__global__ __launch_bounds__(256) void k_pre(const float* __restrict__ inp,
                                             const float* __restrict__ z_e,
                                             const float* __restrict__ cb) {
    __shared__ __align__(16) char sraw[PRE_NZ_BYTES];
    int tid = threadIdx.x;
    int bid = blockIdx.x;

    if (bid < 216) {
        // ---- patterns: 4 voxels/thread, 16 patterns/block ----
        unsigned char* sb = (unsigned char*)sraw;
        int v0 = (bid * 256 + tid) * 4;
        int b = v0 / VOX, s = v0 % VOX;
        const float* p = inp + (size_t)b * 32 * VOX + s;
        float4 x0 = *(const float4*)p;
        float m0 = -1e30f, m1 = -1e30f, m2 = -1e30f, m3 = -1e30f;
        #pragma unroll 4
        for (int c = 1; c < 32; c++) {
            float4 y = *(const float4*)&p[c * VOX];
            m0 = fmaxf(m0, y.x);
            m1 = fmaxf(m1, y.y);
            m2 = fmaxf(m2, y.z);
            m3 = fmaxf(m3, y.w);
        }
        unsigned bits = (m0 > x0.x ? 1u : 0u) | (m1 > x0.y ? 2u : 0u) |
                        (m2 > x0.z ? 4u : 0u) | (m3 > x0.w ? 8u : 0u);
        sb[tid] = (unsigned char)bits;
        __syncthreads();
        if (tid < 16) {
            unsigned long long pat = 0;
            #pragma unroll
            for (int i = 0; i < 16; i++)
                pat |= (unsigned long long)sb[tid * 16 + i] << (4 * i);
            g_pat[bid * 16 + tid] = pat;
        }
        if (bid == 0) {
            for (int i = tid; i < K_CODES; i += 256) g_avgp[i] = 0.f;
            if (tid < 8) g_sums[tid] = 0.f;
            if (tid == 0) g_ctr = 0;
        }
    } else if (bid < 344) {
        // ---- norm_z ----
        int nb = bid - 216;
        float* sm = (float*)sraw;
        float* pnormf = sm + 256 * NZ_PAD;              // [8][32]
        float* norm = pnormf + 8 * 32;                  // [NZ_SCH]
        int b = nb >> 3;
        int s0 = (nb & 7) * NZ_SCH;
        const float* src = z_e + (size_t)b * C_DIM * SPAT + s0;
        for (int i = tid; i < 256 * NZ_SCH; i += 256) {
            int c = i / NZ_SCH, s = i - c * NZ_SCH;
            sm[c * NZ_PAD + s] = src[c * SPAT + s];
        }
        __syncthreads();
        int cg = tid >> 5, lane = tid & 31;
        if (lane < NZ_SCH) {
            float acc = 0.f;
            #pragma unroll
            for (int k = 0; k < 32; k++) {
                float v = sm[(cg * 32 + k) * NZ_PAD + lane];
                acc += v * v;
            }
            pnormf[cg * 32 + lane] = acc;
        }
        __syncthreads();
        if (tid < NZ_SCH) {
            float a = 0.f;
            #pragma unroll
            for (int g = 0; g < 8; g++) a += pnormf[g * 32 + tid];
            norm[tid] = fmaxf(sqrtf(a), 1e-12f);
        }
        __syncthreads();
        for (int i = tid; i < 256 * NZ_SCH; i += 256) {
            int s = i >> 8, c = i & 255;
            float vn = sm[c * NZ_PAD + s] / norm[s];
            int n = b * SPAT + s0 + s;
            g_zn[n * C_DIM + c] = vn;
            __nv_bfloat16 b0, b1;
            bsplit2(vn, b0, b1);
            g_z0[n * C_DIM + c] = b0;
            g_z1[n * C_DIM + c] = b1;
        }
    } else {
        // ---- norm_cb ----
        int k = bid - 344;
        float* red = (float*)sraw;
        float v = cb[k * C_DIM + tid];
        float ss = bsum256(v * v, red);
        float vn = v / fmaxf(sqrtf(ss), 1e-12f);
        g_en[k * C_DIM + tid] = vn;
        __nv_bfloat16 b0, b1;
        bsplit2(vn, b0, b1);
        g_e0[k * C_DIM + tid] = b0;
        g_e1[k * C_DIM + tid] = b1;
    }
}

// =======================================================================
// K_MID: affinity (blocks 0..431) | ham triangle (432..1187, + prefetch)
// =======================================================================
#define AF_PAD 40
#define HM_PAD 72
#define MID_BYTES 31232
__global__ __launch_bounds__(256) void k_mid() {
    __shared__ __align__(16) char sraw[MID_BYTES];
    int tid = threadIdx.x;
    int bid = blockIdx.x;
    int warp = tid >> 5, lane = tid & 31;
    int wi = warp >> 2, wj = warp & 3;

    if (bid < 432) {
        __nv_bfloat16* As0 = (__nv_bfloat16*)sraw;
        __nv_bfloat16* As1 = As0 + 64 * AF_PAD;
        __nv_bfloat16* Bs0 = As1 + 64 * AF_PAD;
        __nv_bfloat16* Bs1 = Bs0 + 128 * AF_PAD;
        __nv_bfloat16* Asp[2] = {As0, As1};
        __nv_bfloat16* Bsp[2] = {Bs0, Bs1};

        int rowBase = (bid >> 3) * 64;
        int colBase = (bid & 7) * 128;
        const __nv_bfloat16* Az0 = g_z0 + rowBase * C_DIM;
        const __nv_bfloat16* Az1 = g_z1 + rowBase * C_DIM;
        const __nv_bfloat16* Be0 = g_e0 + colBase * C_DIM;
        const __nv_bfloat16* Be1 = g_e1 + colBase * C_DIM;

        uint32_t sA[2], sB[2];
        sA[0] = (uint32_t)__cvta_generic_to_shared(As0);
        sA[1] = (uint32_t)__cvta_generic_to_shared(As1);
        sB[0] = (uint32_t)__cvta_generic_to_shared(Bs0);
        sB[1] = (uint32_t)__cvta_generic_to_shared(Bs1);

        int aspl[2], arow[2], apart[2];
        int bspl[4], brow[4], bpart[4];
        #pragma unroll
        for (int i = 0; i < 2; i++) {
            int g = tid + i * 256;
            aspl[i] = g >> 8; int idx = g & 255;
            arow[i] = idx >> 2; apart[i] = idx & 3;
        }
        #pragma unroll
        for (int i = 0; i < 4; i++) {
            int h = tid + i * 256;
            bspl[i] = h >> 9; int idx = h & 511;
            brow[i] = idx >> 2; bpart[i] = idx & 3;
        }

        uint4 pf[6];
        auto loadregs = [&](int kc) {
            #pragma unroll
            for (int i = 0; i < 2; i++) {
                const __nv_bfloat16* base = aspl[i] ? Az1 : Az0;
                pf[i] = *(const uint4*)&base[arow[i] * C_DIM + kc + apart[i] * 8];
            }
            #pragma unroll
            for (int i = 0; i < 4; i++) {
                const __nv_bfloat16* base = bspl[i] ? Be1 : Be0;
                pf[2 + i] = *(const uint4*)&base[brow[i] * C_DIM + kc + bpart[i] * 8];
            }
        };
        auto storeregs = [&]() {
            #pragma unroll
            for (int i = 0; i < 2; i++)
                *(uint4*)&Asp[aspl[i]][arow[i] * AF_PAD + apart[i] * 8] = pf[i];
            #pragma unroll
            for (int i = 0; i < 4; i++)
                *(uint4*)&Bsp[bspl[i]][brow[i] * AF_PAD + bpart[i] * 8] = pf[2 + i];
        };

        float acc[2][4][4] = {};
        loadregs(0);
        storeregs();
        __syncthreads();

        for (int c = 0; c < 8; c++) {
            if (c < 7) loadregs((c + 1) * 32);
            #pragma unroll
            for (int ks = 0; ks < 2; ks++) {
                int k0 = ks * 16;
                uint32_t a[2][2][4], b[2][2][4];
                #pragma unroll
                for (int s = 0; s < 2; s++) {
                    #pragma unroll
                    for (int mt = 0; mt < 2; mt++) {
                        int rb = wi * 32 + mt * 16;
                        uint32_t addr = sA[s] + ((rb + (lane & 15)) * AF_PAD + k0 + (lane >> 4) * 8) * 2;
                        ldsm_x4(a[s][mt][0], a[s][mt][1], a[s][mt][2], a[s][mt][3], addr);
                    }
                    #pragma unroll
                    for (int ng = 0; ng < 2; ng++) {
                        int row = wj * 32 + ng * 16 + (lane & 7) + ((lane >> 4) << 3);
                        int koff = k0 + ((lane >> 3) & 1) * 8;
                        uint32_t addr = sB[s] + (row * AF_PAD + koff) * 2;
                        ldsm_x4(b[s][ng][0], b[s][ng][1], b[s][ng][2], b[s][ng][3], addr);
                    }
                }
                #pragma unroll
                for (int mt = 0; mt < 2; mt++)
                    #pragma unroll
                    for (int nt = 0; nt < 4; nt++) {
                        int ng = nt >> 1, off = (nt & 1) * 2;
                        float* cc = acc[mt][nt];
                        mma_bf16(cc, a[0][mt][0], a[0][mt][1], a[0][mt][2], a[0][mt][3],
                                 b[0][ng][off], b[0][ng][off + 1]);
                        mma_bf16(cc, a[0][mt][0], a[0][mt][1], a[0][mt][2], a[0][mt][3],
                                 b[1][ng][off], b[1][ng][off + 1]);
                        mma_bf16(cc, a[1][mt][0], a[1][mt][1], a[1][mt][2], a[1][mt][3],
                                 b[0][ng][off], b[0][ng][off + 1]);
                    }
            }
            __syncthreads();
            if (c < 7) {
                storeregs();
                __syncthreads();
            }
        }

        #pragma unroll
        for (int mt = 0; mt < 2; mt++) {
            #pragma unroll
            for (int nt = 0; nt < 4; nt++) {
                int i0 = rowBase + wi * 32 + mt * 16 + (lane >> 2);
                int j0 = colBase + wj * 32 + nt * 8 + (lane & 3) * 2;
                *(float2*)&g_aff[i0 * K_CODES + j0] = make_float2(acc[mt][nt][0], acc[mt][nt][1]);
                *(float2*)&g_aff[(i0 + 8) * K_CODES + j0] = make_float2(acc[mt][nt][2], acc[mt][nt][3]);
            }
        }
    } else {
        int id = bid - 432;
        int jt = (int)((sqrtf(4.f * id + 1.f) - 1.f) * 0.5f);
        while (jt * jt + jt > id) jt--;
        while ((jt + 1) * (jt + 1) + (jt + 1) <= id) jt++;
        int it = id - (jt * jt + jt);

        __nv_bfloat16* Ahs = (__nv_bfloat16*)sraw;
        __nv_bfloat16* Bhs = Ahs + 64 * HM_PAD;
        unsigned long long* spi = (unsigned long long*)(Bhs + 128 * HM_PAD);
        unsigned long long* spj = spi + 64;
        float* red = (float*)(spj + 128);

        const __nv_bfloat16* Ag = g_z0 + it * 64 * C_DIM;
        const __nv_bfloat16* Bg = g_z0 + jt * 128 * C_DIM;
        if (tid < 64)        spi[tid] = g_pat[it * 64 + tid];
        else if (tid < 192)  spj[tid - 64] = g_pat[jt * 128 + tid - 64];

        uint32_t sA = (uint32_t)__cvta_generic_to_shared(Ahs);
        uint32_t sB = (uint32_t)__cvta_generic_to_shared(Bhs);
        float acc[2][4][4] = {};

        // per-thread load slots: 6 uint4 (A: 512, B: 1024)
        int hisB[6], hrow[6], hpart[6];
        #pragma unroll
        for (int i = 0; i < 6; i++) {
            int g = tid + i * 256;
            if (g < 512) { hisB[i] = 0; hrow[i] = g >> 3; hpart[i] = g & 7; }
            else { int h = g - 512; hisB[i] = 1; hrow[i] = h >> 3; hpart[i] = h & 7; }
        }
        uint4 hpf[6];
        auto hload = [&](int kc) {
            #pragma unroll
            for (int i = 0; i < 6; i++) {
                const __nv_bfloat16* base = hisB[i] ? Bg : Ag;
                hpf[i] = *(const uint4*)&base[hrow[i] * C_DIM + kc + hpart[i] * 8];
            }
        };
        auto hstore = [&]() {
            #pragma unroll
            for (int i = 0; i < 6; i++) {
                __nv_bfloat16* dst = hisB[i] ? Bhs : Ahs;
                *(uint4*)&dst[hrow[i] * HM_PAD + hpart[i] * 8] = hpf[i];
            }
        };

        hload(0);
        hstore();
        __syncthreads();

        for (int c = 0; c < 4; c++) {
            if (c < 3) hload((c + 1) * 64);   // issue next-chunk LDGs before compute
            #pragma unroll
            for (int ks = 0; ks < 4; ks++) {
                int k0 = ks * 16;
                uint32_t a[2][4], b[2][4];
                #pragma unroll
                for (int mt = 0; mt < 2; mt++) {
                    int rb = wi * 32 + mt * 16;
                    uint32_t addr = sA + ((rb + (lane & 15)) * HM_PAD + k0 + (lane >> 4) * 8) * 2;
                    ldsm_x4(a[mt][0], a[mt][1], a[mt][2], a[mt][3], addr);
                }
                #pragma unroll
                for (int ng = 0; ng < 2; ng++) {
                    int row = wj * 32 + ng * 16 + (lane & 7) + ((lane >> 4) << 3);
                    int koff = k0 + ((lane >> 3) & 1) * 8;
                    uint32_t addr = sB + (row * HM_PAD + koff) * 2;
                    ldsm_x4(b[ng][0], b[ng][1], b[ng][2], b[ng][3], addr);
                }
                #pragma unroll
                for (int mt = 0; mt < 2; mt++)
                    #pragma unroll
                    for (int nt = 0; nt < 4; nt++) {
                        int ng = nt >> 1, off = (nt & 1) * 2;
                        mma_bf16(acc[mt][nt], a[mt][0], a[mt][1], a[mt][2], a[mt][3],
                                 b[ng][off], b[ng][off + 1]);
                    }
            }
            __syncthreads();
            if (c < 3) {
                hstore();
                __syncthreads();
            }
        }

        float ws = 0.f, wc = 0.f;
        #pragma unroll
        for (int mt = 0; mt < 2; mt++) {
            #pragma unroll
            for (int nt = 0; nt < 4; nt++) {
                int li0 = wi * 32 + mt * 16 + (lane >> 2);
                int lj0 = wj * 32 + nt * 8 + (lane & 3) * 2;
                #pragma unroll
                for (int hh = 0; hh < 2; hh++) {
                    int li = li0 + hh * 8;
                    int gi = it * 64 + li;
                    unsigned long long pi = spi[li];
                    #pragma unroll
                    for (int jj = 0; jj < 2; jj++) {
                        int lj = lj0 + jj;
                        int gj = jt * 128 + lj;
                        int h = __popcll(pi ^ spj[lj]);
                        if (gj > gi && h <= 5) {
                            float w = 1.0f - (float)h * (1.0f / 64.0f);
                            ws += w;
                            wc += w * acc[mt][nt][hh * 2 + jj];
                        }
                    }
                }
            }
        }
        float wsb = bsum256(ws * 2.0f, red);
        float wcb = bsum256(wc * 2.0f, red);
        if (tid == 0) {
            atomicAdd(&g_sums[2], wsb);
            atomicAdd(&g_sums[3], wcb);
        }
    }
}

// =======================================================================
// K_POST: per-row pass (R10-exact) + last-block final combine
// =======================================================================
#define ROWS_PB 8
__global__ __launch_bounds__(256) void k_post(float* __restrict__ out) {
    int n0 = blockIdx.x * ROWS_PB, t = threadIdx.x;
    __shared__ float redA[8], redB[8], redC[8];
    __shared__ float redm[8];
    __shared__ int   redi[8];
    __shared__ float zqs[ROWS_PB][C_DIM + 1];
    __shared__ int slast;

    float avg_acc[4] = {0.f, 0.f, 0.f, 0.f};
    float ent_acc = 0.f, sse_acc = 0.f;

    for (int rr = 0; rr < ROWS_PB; rr++) {
        int n = n0 + rr;
        float fa[4];
        #pragma unroll
        for (int q = 0; q < 4; q++)
            fa[q] = g_aff[n * K_CODES + t + q * 256] * 100.0f;

        float m = fa[0]; int mi = t;
        #pragma unroll
        for (int q = 1; q < 4; q++)
            if (fa[q] > m) { m = fa[q]; mi = t + q * 256; }
        #pragma unroll
        for (int o = 16; o; o >>= 1) {
            float om = __shfl_xor_sync(0xffffffffu, m, o);
            int   oi = __shfl_xor_sync(0xffffffffu, mi, o);
            if (om > m || (om == m && oi < mi)) { m = om; mi = oi; }
        }
        if ((t & 31) == 0) { redm[t >> 5] = m; redi[t >> 5] = mi; }
        __syncthreads();
        float bm = redm[0]; int bidx = redi[0];
        #pragma unroll
        for (int w = 1; w < 8; w++)
            if (redm[w] > bm || (redm[w] == bm && redi[w] < bidx)) { bm = redm[w]; bidx = redi[w]; }

        float e[4], se = 0.f, te = 0.f;
        #pragma unroll
        for (int q = 0; q < 4; q++) {
            float d = fa[q] - bm;
            e[q] = fexp(d);
            se += e[q];
            te += e[q] * d;
        }
        float zq = g_en[bidx * C_DIM + t];
        float zn = g_zn[n * C_DIM + t];
        zqs[rr][t] = zq;
        float dd = zq - zn;
        float v0 = se, v1 = te, v2 = dd * dd;
        #pragma unroll
        for (int o = 16; o; o >>= 1) {
            v0 += __shfl_xor_sync(0xffffffffu, v0, o);
            v1 += __shfl_xor_sync(0xffffffffu, v1, o);
            v2 += __shfl_xor_sync(0xffffffffu, v2, o);
        }
        __syncthreads();
        if ((t & 31) == 0) { redA[t >> 5] = v0; redB[t >> 5] = v1; redC[t >> 5] = v2; }
        __syncthreads();
        float Z = 0.f, T = 0.f, S = 0.f;
        #pragma unroll
        for (int w = 0; w < 8; w++) { Z += redA[w]; T += redB[w]; S += redC[w]; }

        if (t == 0) {
            ent_acc += logf(Z) - T / Z;
            sse_acc += S;
            out[OUT_IDX + n] = (float)bidx;
        }
        float invZ = 1.0f / Z;
        #pragma unroll
        for (int q = 0; q < 4; q++) avg_acc[q] += e[q] * invZ;
        __syncthreads();
    }

    // coalesced z_q write
    {
        int b = n0 / SPAT, s0 = n0 % SPAT;
        float* dst = out + ((size_t)b * C_DIM) * SPAT + s0;
        for (int i = t; i < C_DIM * ROWS_PB; i += 256) {
            int c = i >> 3, rr = i & 7;
            dst[c * SPAT + rr] = zqs[rr][c];
        }
    }

    const float invN = 1.0f / (float)N_ROWS;
    #pragma unroll
    for (int q = 0; q < 4; q++)
        atomicAdd(&g_avgp[t + q * 256], avg_acc[q] * invN);
    if (t == 0) {
        atomicAdd(&g_sums[1], ent_acc);
        atomicAdd(&g_sums[0], sse_acc);
    }

    // ---- last block performs final combine ----
    __threadfence();
    if (t == 0) {
        int old = atomicAdd(&g_ctr, 1);
        slast = (old == (int)gridDim.x - 1) ? 1 : 0;
    }
    __syncthreads();
    if (slast) {
        __threadfence();
        float v = 0.f;
        #pragma unroll
        for (int q = 0; q < 4; q++) {
            float p = g_avgp[t + q * 256];
            v += p * logf(p + 1e-5f);
        }
        float s = bsum256(v, redA);
        if (t == 0) {
            float sseT = g_sums[0];
            float sent = g_sums[1];
            float sw   = g_sums[2];
            float swc  = g_sums[3];
            float codebook_loss = sseT / (float)(N_ROWS * C_DIM);
            float commit_loss   = 0.25f * codebook_loss;
            float sample_entropy = sent / (float)N_ROWS;
            float avg_entropy    = -s;
            float ent_loss = 0.1f * (sample_entropy - avg_entropy);
            float ham_loss = (sw - swc) / (sw + 1e-8f);
            out[OUT_LOSS] = codebook_loss + commit_loss + ent_loss + ham_loss;
        }
    }
}

// ---------------- launch ----------------
extern "C" void kernel_launch(void* const* d_in, const int* in_sizes, int n_in,
                              void* d_out, int out_size) {
    const float* input_blocks = (const float*)d_in[0];
    const float* z_e          = (const float*)d_in[1];
    const float* codebook     = (const float*)d_in[2];
    float* out = (float*)d_out;

    k_pre<<<1368, 256>>>(input_blocks, z_e, codebook);
    k_mid<<<1188, 256>>>();
    k_post<<<N_ROWS / ROWS_PB, 256>>>(out);
}

// round 14
// speedup vs baseline: 1.0689x; 1.0067x over previous
#include <cuda_runtime.h>
#include <cuda_bf16.h>
#include <math.h>
#include <stdint.h>

#define N_ROWS 3456      // 16 * 216
#define C_DIM  256
#define K_CODES 1024
#define B_SZ   16
#define SPAT   216       // 6*6*6
#define VOX    13824     // 24^3
#define OUT_ZQ (B_SZ * C_DIM * SPAT)   // 884736
#define OUT_LOSS OUT_ZQ
#define OUT_IDX (OUT_ZQ + 1)

// ---------------- device scratch ----------------
__device__ float g_zn[N_ROWS * C_DIM];
__device__ __nv_bfloat16 g_z0[N_ROWS * C_DIM];
__device__ __nv_bfloat16 g_z1[N_ROWS * C_DIM];
__device__ float g_en[K_CODES * C_DIM];
__device__ __nv_bfloat16 g_e0[K_CODES * C_DIM];
__device__ __nv_bfloat16 g_e1[K_CODES * C_DIM];
__device__ float g_aff[N_ROWS * K_CODES];
__device__ unsigned long long g_pat[N_ROWS];
__device__ float g_avgp[K_CODES];
__device__ float g_sums[8];   // 0: SSE, 1: entropy sum, 2: sumW, 3: sumWcos
__device__ int g_ctr;

// ---------------- helpers ----------------
__device__ __forceinline__ float bsum256(float v, float* red) {
    #pragma unroll
    for (int o = 16; o; o >>= 1) v += __shfl_xor_sync(0xffffffffu, v, o);
    __syncthreads();
    if ((threadIdx.x & 31) == 0) red[threadIdx.x >> 5] = v;
    __syncthreads();
    float s = 0.f;
    #pragma unroll
    for (int w = 0; w < 8; w++) s += red[w];
    return s;
}

__device__ __forceinline__ float fexp(float d) {   // e^d for d <= 0
    float r;
    asm("ex2.approx.f32 %0, %1;" : "=f"(r) : "f"(d * 1.4426950408889634f));
    return r;
}

__device__ __forceinline__ void ldsm_x4(uint32_t& r0, uint32_t& r1, uint32_t& r2, uint32_t& r3, uint32_t addr) {
    asm volatile("ldmatrix.sync.aligned.m8n8.x4.shared.b16 {%0,%1,%2,%3}, [%4];"
                 : "=r"(r0), "=r"(r1), "=r"(r2), "=r"(r3) : "r"(addr));
}
__device__ __forceinline__ void mma_bf16(float* c, uint32_t a0, uint32_t a1, uint32_t a2, uint32_t a3,
                                         uint32_t b0, uint32_t b1) {
    asm volatile("mma.sync.aligned.m16n8k16.row.col.f32.bf16.bf16.f32 "
                 "{%0,%1,%2,%3}, {%4,%5,%6,%7}, {%8,%9}, {%0,%1,%2,%3};"
                 : "+f"(c[0]), "+f"(c[1]), "+f"(c[2]), "+f"(c[3])
                 : "r"(a0), "r"(a1), "r"(a2), "r"(a3), "r"(b0), "r"(b1));
}

__device__ __forceinline__ void bsplit2(float x, __nv_bfloat16& b0, __nv_bfloat16& b1) {
    b0 = __float2bfloat16_rn(x);
    b1 = __float2bfloat16_rn(x - __bfloat162float(b0));
}

// =======================================================================
// K_PRE: pattern (blocks 0..215) | norm_z (216..343) | norm_cb (344..1367)
// =======================================================================
#define NZ_SCH 27
#define NZ_PAD 29
#define PRE_NZ_BYTES (256 * NZ_PAD * 4 + 8 * 32 * 4 + NZ_SCH * 4 + 64)
__global__ __launch_bounds__(256) void k_pre(const float* __restrict__ inp,
                                             const float* __restrict__ z_e,
                                             const float* __restrict__ cb) {
    __shared__ __align__(16) char sraw[PRE_NZ_BYTES];
    int tid = threadIdx.x;
    int bid = blockIdx.x;

    if (bid < 216) {
        // ---- patterns: 4 voxels/thread, 16 patterns/block ----
        unsigned char* sb = (unsigned char*)sraw;
        int v0 = (bid * 256 + tid) * 4;
        int b = v0 / VOX, s = v0 % VOX;
        const float* p = inp + (size_t)b * 32 * VOX + s;
        float4 x0 = *(const float4*)p;
        float m0 = -1e30f, m1 = -1e30f, m2 = -1e30f, m3 = -1e30f;
        #pragma unroll 4
        for (int c = 1; c < 32; c++) {
            float4 y = *(const float4*)&p[c * VOX];
            m0 = fmaxf(m0, y.x);
            m1 = fmaxf(m1, y.y);
            m2 = fmaxf(m2, y.z);
            m3 = fmaxf(m3, y.w);
        }
        unsigned bits = (m0 > x0.x ? 1u : 0u) | (m1 > x0.y ? 2u : 0u) |
                        (m2 > x0.z ? 4u : 0u) | (m3 > x0.w ? 8u : 0u);
        sb[tid] = (unsigned char)bits;
        __syncthreads();
        if (tid < 16) {
            unsigned long long pat = 0;
            #pragma unroll
            for (int i = 0; i < 16; i++)
                pat |= (unsigned long long)sb[tid * 16 + i] << (4 * i);
            g_pat[bid * 16 + tid] = pat;
        }
        if (bid == 0) {
            for (int i = tid; i < K_CODES; i += 256) g_avgp[i] = 0.f;
            if (tid < 8) g_sums[tid] = 0.f;
            if (tid == 0) g_ctr = 0;
        }
    } else if (bid < 344) {
        // ---- norm_z ----
        int nb = bid - 216;
        float* sm = (float*)sraw;
        float* pnormf = sm + 256 * NZ_PAD;              // [8][32]
        float* norm = pnormf + 8 * 32;                  // [NZ_SCH]
        int b = nb >> 3;
        int s0 = (nb & 7) * NZ_SCH;
        const float* src = z_e + (size_t)b * C_DIM * SPAT + s0;
        for (int i = tid; i < 256 * NZ_SCH; i += 256) {
            int c = i / NZ_SCH, s = i - c * NZ_SCH;
            sm[c * NZ_PAD + s] = src[c * SPAT + s];
        }
        __syncthreads();
        int cg = tid >> 5, lane = tid & 31;
        if (lane < NZ_SCH) {
            float acc = 0.f;
            #pragma unroll
            for (int k = 0; k < 32; k++) {
                float v = sm[(cg * 32 + k) * NZ_PAD + lane];
                acc += v * v;
            }
            pnormf[cg * 32 + lane] = acc;
        }
        __syncthreads();
        if (tid < NZ_SCH) {
            float a = 0.f;
            #pragma unroll
            for (int g = 0; g < 8; g++) a += pnormf[g * 32 + tid];
            norm[tid] = fmaxf(sqrtf(a), 1e-12f);
        }
        __syncthreads();
        for (int i = tid; i < 256 * NZ_SCH; i += 256) {
            int s = i >> 8, c = i & 255;
            float vn = sm[c * NZ_PAD + s] / norm[s];
            int n = b * SPAT + s0 + s;
            g_zn[n * C_DIM + c] = vn;
            __nv_bfloat16 b0, b1;
            bsplit2(vn, b0, b1);
            g_z0[n * C_DIM + c] = b0;
            g_z1[n * C_DIM + c] = b1;
        }
    } else {
        // ---- norm_cb ----
        int k = bid - 344;
        float* red = (float*)sraw;
        float v = cb[k * C_DIM + tid];
        float ss = bsum256(v * v, red);
        float vn = v / fmaxf(sqrtf(ss), 1e-12f);
        g_en[k * C_DIM + tid] = vn;
        __nv_bfloat16 b0, b1;
        bsplit2(vn, b0, b1);
        g_e0[k * C_DIM + tid] = b0;
        g_e1[k * C_DIM + tid] = b1;
    }
}

// =======================================================================
// K_MID: affinity (blocks 0..431) | ham triangle (432..1187, prefetch)
// =======================================================================
#define AF_PAD 40
#define HM_PAD 72
#define MID_BYTES 31232
__global__ __launch_bounds__(256) void k_mid() {
    __shared__ __align__(16) char sraw[MID_BYTES];
    int tid = threadIdx.x;
    int bid = blockIdx.x;
    int warp = tid >> 5, lane = tid & 31;
    int wi = warp >> 2, wj = warp & 3;

    if (bid < 432) {
        __nv_bfloat16* As0 = (__nv_bfloat16*)sraw;
        __nv_bfloat16* As1 = As0 + 64 * AF_PAD;
        __nv_bfloat16* Bs0 = As1 + 64 * AF_PAD;
        __nv_bfloat16* Bs1 = Bs0 + 128 * AF_PAD;
        __nv_bfloat16* Asp[2] = {As0, As1};
        __nv_bfloat16* Bsp[2] = {Bs0, Bs1};

        int rowBase = (bid >> 3) * 64;
        int colBase = (bid & 7) * 128;
        const __nv_bfloat16* Az0 = g_z0 + rowBase * C_DIM;
        const __nv_bfloat16* Az1 = g_z1 + rowBase * C_DIM;
        const __nv_bfloat16* Be0 = g_e0 + colBase * C_DIM;
        const __nv_bfloat16* Be1 = g_e1 + colBase * C_DIM;

        uint32_t sA[2], sB[2];
        sA[0] = (uint32_t)__cvta_generic_to_shared(As0);
        sA[1] = (uint32_t)__cvta_generic_to_shared(As1);
        sB[0] = (uint32_t)__cvta_generic_to_shared(Bs0);
        sB[1] = (uint32_t)__cvta_generic_to_shared(Bs1);

        int aspl[2], arow[2], apart[2];
        int bspl[4], brow[4], bpart[4];
        #pragma unroll
        for (int i = 0; i < 2; i++) {
            int g = tid + i * 256;
            aspl[i] = g >> 8; int idx = g & 255;
            arow[i] = idx >> 2; apart[i] = idx & 3;
        }
        #pragma unroll
        for (int i = 0; i < 4; i++) {
            int h = tid + i * 256;
            bspl[i] = h >> 9; int idx = h & 511;
            brow[i] = idx >> 2; bpart[i] = idx & 3;
        }

        uint4 pf[6];
        auto loadregs = [&](int kc) {
            #pragma unroll
            for (int i = 0; i < 2; i++) {
                const __nv_bfloat16* base = aspl[i] ? Az1 : Az0;
                pf[i] = *(const uint4*)&base[arow[i] * C_DIM + kc + apart[i] * 8];
            }
            #pragma unroll
            for (int i = 0; i < 4; i++) {
                const __nv_bfloat16* base = bspl[i] ? Be1 : Be0;
                pf[2 + i] = *(const uint4*)&base[brow[i] * C_DIM + kc + bpart[i] * 8];
            }
        };
        auto storeregs = [&]() {
            #pragma unroll
            for (int i = 0; i < 2; i++)
                *(uint4*)&Asp[aspl[i]][arow[i] * AF_PAD + apart[i] * 8] = pf[i];
            #pragma unroll
            for (int i = 0; i < 4; i++)
                *(uint4*)&Bsp[bspl[i]][brow[i] * AF_PAD + bpart[i] * 8] = pf[2 + i];
        };

        float acc[2][4][4] = {};
        loadregs(0);
        storeregs();
        __syncthreads();

        for (int c = 0; c < 8; c++) {
            if (c < 7) loadregs((c + 1) * 32);
            #pragma unroll
            for (int ks = 0; ks < 2; ks++) {
                int k0 = ks * 16;
                uint32_t a[2][2][4], b[2][2][4];
                #pragma unroll
                for (int s = 0; s < 2; s++) {
                    #pragma unroll
                    for (int mt = 0; mt < 2; mt++) {
                        int rb = wi * 32 + mt * 16;
                        uint32_t addr = sA[s] + ((rb + (lane & 15)) * AF_PAD + k0 + (lane >> 4) * 8) * 2;
                        ldsm_x4(a[s][mt][0], a[s][mt][1], a[s][mt][2], a[s][mt][3], addr);
                    }
                    #pragma unroll
                    for (int ng = 0; ng < 2; ng++) {
                        int row = wj * 32 + ng * 16 + (lane & 7) + ((lane >> 4) << 3);
                        int koff = k0 + ((lane >> 3) & 1) * 8;
                        uint32_t addr = sB[s] + (row * AF_PAD + koff) * 2;
                        ldsm_x4(b[s][ng][0], b[s][ng][1], b[s][ng][2], b[s][ng][3], addr);
                    }
                }
                #pragma unroll
                for (int mt = 0; mt < 2; mt++)
                    #pragma unroll
                    for (int nt = 0; nt < 4; nt++) {
                        int ng = nt >> 1, off = (nt & 1) * 2;
                        float* cc = acc[mt][nt];
                        mma_bf16(cc, a[0][mt][0], a[0][mt][1], a[0][mt][2], a[0][mt][3],
                                 b[0][ng][off], b[0][ng][off + 1]);
                        mma_bf16(cc, a[0][mt][0], a[0][mt][1], a[0][mt][2], a[0][mt][3],
                                 b[1][ng][off], b[1][ng][off + 1]);
                        mma_bf16(cc, a[1][mt][0], a[1][mt][1], a[1][mt][2], a[1][mt][3],
                                 b[0][ng][off], b[0][ng][off + 1]);
                    }
            }
            __syncthreads();
            if (c < 7) {
                storeregs();
                __syncthreads();
            }
        }

        #pragma unroll
        for (int mt = 0; mt < 2; mt++) {
            #pragma unroll
            for (int nt = 0; nt < 4; nt++) {
                int i0 = rowBase + wi * 32 + mt * 16 + (lane >> 2);
                int j0 = colBase + wj * 32 + nt * 8 + (lane & 3) * 2;
                *(float2*)&g_aff[i0 * K_CODES + j0] = make_float2(acc[mt][nt][0], acc[mt][nt][1]);
                *(float2*)&g_aff[(i0 + 8) * K_CODES + j0] = make_float2(acc[mt][nt][2], acc[mt][nt][3]);
            }
        }
    } else {
        int id = bid - 432;
        int jt = (int)((sqrtf(4.f * id + 1.f) - 1.f) * 0.5f);
        while (jt * jt + jt > id) jt--;
        while ((jt + 1) * (jt + 1) + (jt + 1) <= id) jt++;
        int it = id - (jt * jt + jt);

        __nv_bfloat16* Ahs = (__nv_bfloat16*)sraw;
        __nv_bfloat16* Bhs = Ahs + 64 * HM_PAD;
        unsigned long long* spi = (unsigned long long*)(Bhs + 128 * HM_PAD);
        unsigned long long* spj = spi + 64;
        float* red = (float*)(spj + 128);

        const __nv_bfloat16* Ag = g_z0 + it * 64 * C_DIM;
        const __nv_bfloat16* Bg = g_z0 + jt * 128 * C_DIM;
        if (tid < 64)        spi[tid] = g_pat[it * 64 + tid];
        else if (tid < 192)  spj[tid - 64] = g_pat[jt * 128 + tid - 64];

        uint32_t sA = (uint32_t)__cvta_generic_to_shared(Ahs);
        uint32_t sB = (uint32_t)__cvta_generic_to_shared(Bhs);
        float acc[2][4][4] = {};

        int hisB[6], hrow[6], hpart[6];
        #pragma unroll
        for (int i = 0; i < 6; i++) {
            int g = tid + i * 256;
            if (g < 512) { hisB[i] = 0; hrow[i] = g >> 3; hpart[i] = g & 7; }
            else { int h = g - 512; hisB[i] = 1; hrow[i] = h >> 3; hpart[i] = h & 7; }
        }
        uint4 hpf[6];
        auto hload = [&](int kc) {
            #pragma unroll
            for (int i = 0; i < 6; i++) {
                const __nv_bfloat16* base = hisB[i] ? Bg : Ag;
                hpf[i] = *(const uint4*)&base[hrow[i] * C_DIM + kc + hpart[i] * 8];
            }
        };
        auto hstore = [&]() {
            #pragma unroll
            for (int i = 0; i < 6; i++) {
                __nv_bfloat16* dst = hisB[i] ? Bhs : Ahs;
                *(uint4*)&dst[hrow[i] * HM_PAD + hpart[i] * 8] = hpf[i];
            }
        };

        hload(0);
        hstore();
        __syncthreads();

        for (int c = 0; c < 4; c++) {
            if (c < 3) hload((c + 1) * 64);
            #pragma unroll
            for (int ks = 0; ks < 4; ks++) {
                int k0 = ks * 16;
                uint32_t a[2][4], b[2][4];
                #pragma unroll
                for (int mt = 0; mt < 2; mt++) {
                    int rb = wi * 32 + mt * 16;
                    uint32_t addr = sA + ((rb + (lane & 15)) * HM_PAD + k0 + (lane >> 4) * 8) * 2;
                    ldsm_x4(a[mt][0], a[mt][1], a[mt][2], a[mt][3], addr);
                }
                #pragma unroll
                for (int ng = 0; ng < 2; ng++) {
                    int row = wj * 32 + ng * 16 + (lane & 7) + ((lane >> 4) << 3);
                    int koff = k0 + ((lane >> 3) & 1) * 8;
                    uint32_t addr = sB + (row * HM_PAD + koff) * 2;
                    ldsm_x4(b[ng][0], b[ng][1], b[ng][2], b[ng][3], addr);
                }
                #pragma unroll
                for (int mt = 0; mt < 2; mt++)
                    #pragma unroll
                    for (int nt = 0; nt < 4; nt++) {
                        int ng = nt >> 1, off = (nt & 1) * 2;
                        mma_bf16(acc[mt][nt], a[mt][0], a[mt][1], a[mt][2], a[mt][3],
                                 b[ng][off], b[ng][off + 1]);
                    }
            }
            __syncthreads();
            if (c < 3) {
                hstore();
                __syncthreads();
            }
        }

        float ws = 0.f, wc = 0.f;
        #pragma unroll
        for (int mt = 0; mt < 2; mt++) {
            #pragma unroll
            for (int nt = 0; nt < 4; nt++) {
                int li0 = wi * 32 + mt * 16 + (lane >> 2);
                int lj0 = wj * 32 + nt * 8 + (lane & 3) * 2;
                #pragma unroll
                for (int hh = 0; hh < 2; hh++) {
                    int li = li0 + hh * 8;
                    int gi = it * 64 + li;
                    unsigned long long pi = spi[li];
                    #pragma unroll
                    for (int jj = 0; jj < 2; jj++) {
                        int lj = lj0 + jj;
                        int gj = jt * 128 + lj;
                        int h = __popcll(pi ^ spj[lj]);
                        if (gj > gi && h <= 5) {
                            float w = 1.0f - (float)h * (1.0f / 64.0f);
                            ws += w;
                            wc += w * acc[mt][nt][hh * 2 + jj];
                        }
                    }
                }
            }
        }
        float wsb = bsum256(ws * 2.0f, red);
        float wcb = bsum256(wc * 2.0f, red);
        if (tid == 0) {
            atomicAdd(&g_sums[2], wsb);
            atomicAdd(&g_sums[3], wcb);
        }
    }
}

// =======================================================================
// K_POST: per-row pass with row prefetch + last-block final combine
// =======================================================================
#define ROWS_PB 8
__global__ __launch_bounds__(256) void k_post(float* __restrict__ out) {
    int n0 = blockIdx.x * ROWS_PB, t = threadIdx.x;
    __shared__ float redA[8], redB[8], redC[8];
    __shared__ float redm[8];
    __shared__ int   redi[8];
    __shared__ float zqs[ROWS_PB][C_DIM + 1];
    __shared__ int slast;

    float avg_acc[4] = {0.f, 0.f, 0.f, 0.f};
    float ent_acc = 0.f, sse_acc = 0.f;

    // prefetch row 0
    float fa[4], fan[4];
    #pragma unroll
    for (int q = 0; q < 4; q++)
        fa[q] = g_aff[n0 * K_CODES + t + q * 256] * 100.0f;

    for (int rr = 0; rr < ROWS_PB; rr++) {
        int n = n0 + rr;
        // issue next row's loads before this row's reduction chain
        if (rr + 1 < ROWS_PB) {
            #pragma unroll
            for (int q = 0; q < 4; q++)
                fan[q] = g_aff[(n + 1) * K_CODES + t + q * 256] * 100.0f;
        }

        float m = fa[0]; int mi = t;
        #pragma unroll
        for (int q = 1; q < 4; q++)
            if (fa[q] > m) { m = fa[q]; mi = t + q * 256; }
        #pragma unroll
        for (int o = 16; o; o >>= 1) {
            float om = __shfl_xor_sync(0xffffffffu, m, o);
            int   oi = __shfl_xor_sync(0xffffffffu, mi, o);
            if (om > m || (om == m && oi < mi)) { m = om; mi = oi; }
        }
        if ((t & 31) == 0) { redm[t >> 5] = m; redi[t >> 5] = mi; }
        __syncthreads();
        float bm = redm[0]; int bidx = redi[0];
        #pragma unroll
        for (int w = 1; w < 8; w++)
            if (redm[w] > bm || (redm[w] == bm && redi[w] < bidx)) { bm = redm[w]; bidx = redi[w]; }

        float e[4], se = 0.f, te = 0.f;
        #pragma unroll
        for (int q = 0; q < 4; q++) {
            float d = fa[q] - bm;
            e[q] = fexp(d);
            se += e[q];
            te += e[q] * d;
        }
        float zq = g_en[bidx * C_DIM + t];
        float zn = g_zn[n * C_DIM + t];
        zqs[rr][t] = zq;
        float dd = zq - zn;
        float v0 = se, v1 = te, v2 = dd * dd;
        #pragma unroll
        for (int o = 16; o; o >>= 1) {
            v0 += __shfl_xor_sync(0xffffffffu, v0, o);
            v1 += __shfl_xor_sync(0xffffffffu, v1, o);
            v2 += __shfl_xor_sync(0xffffffffu, v2, o);
        }
        __syncthreads();
        if ((t & 31) == 0) { redA[t >> 5] = v0; redB[t >> 5] = v1; redC[t >> 5] = v2; }
        __syncthreads();
        float Z = 0.f, T = 0.f, S = 0.f;
        #pragma unroll
        for (int w = 0; w < 8; w++) { Z += redA[w]; T += redB[w]; S += redC[w]; }

        if (t == 0) {
            ent_acc += logf(Z) - T / Z;
            sse_acc += S;
            out[OUT_IDX + n] = (float)bidx;
        }
        float invZ = 1.0f / Z;
        #pragma unroll
        for (int q = 0; q < 4; q++) avg_acc[q] += e[q] * invZ;

        #pragma unroll
        for (int q = 0; q < 4; q++) fa[q] = fan[q];
        __syncthreads();
    }

    // coalesced z_q write
    {
        int b = n0 / SPAT, s0 = n0 % SPAT;
        float* dst = out + ((size_t)b * C_DIM) * SPAT + s0;
        for (int i = t; i < C_DIM * ROWS_PB; i += 256) {
            int c = i >> 3, rr = i & 7;
            dst[c * SPAT + rr] = zqs[rr][c];
        }
    }

    const float invN = 1.0f / (float)N_ROWS;
    #pragma unroll
    for (int q = 0; q < 4; q++)
        atomicAdd(&g_avgp[t + q * 256], avg_acc[q] * invN);
    if (t == 0) {
        atomicAdd(&g_sums[1], ent_acc);
        atomicAdd(&g_sums[0], sse_acc);
    }

    // ---- last block performs final combine ----
    __threadfence();
    if (t == 0) {
        int old = atomicAdd(&g_ctr, 1);
        slast = (old == (int)gridDim.x - 1) ? 1 : 0;
    }
    __syncthreads();
    if (slast) {
        __threadfence();
        float v = 0.f;
        #pragma unroll
        for (int q = 0; q < 4; q++) {
            float p = g_avgp[t + q * 256];
            v += p * logf(p + 1e-5f);
        }
        float s = bsum256(v, redA);
        if (t == 0) {
            float sseT = g_sums[0];
            float sent = g_sums[1];
            float sw   = g_sums[2];
            float swc  = g_sums[3];
            float codebook_loss = sseT / (float)(N_ROWS * C_DIM);
            float commit_loss   = 0.25f * codebook_loss;
            float sample_entropy = sent / (float)N_ROWS;
            float avg_entropy    = -s;
            float ent_loss = 0.1f * (sample_entropy - avg_entropy);
            float ham_loss = (sw - swc) / (sw + 1e-8f);
            out[OUT_LOSS] = codebook_loss + commit_loss + ent_loss + ham_loss;
        }
    }
}

// ---------------- launch ----------------
extern "C" void kernel_launch(void* const* d_in, const int* in_sizes, int n_in,
                              void* d_out, int out_size) {
    const float* input_blocks = (const float*)d_in[0];
    const float* z_e          = (const float*)d_in[1];
    const float* codebook     = (const float*)d_in[2];
    float* out = (float*)d_out;

    k_pre<<<1368, 256>>>(input_blocks, z_e, codebook);
    k_mid<<<1188, 256>>>();
    k_post<<<N_ROWS / ROWS_PB, 256>>>(out);
}

// round 15
// speedup vs baseline: 1.1372x; 1.0639x over previous
#include <cuda_runtime.h>
#include <cuda_bf16.h>
#include <math.h>
#include <stdint.h>

#define N_ROWS 3456      // 16 * 216
#define C_DIM  256
#define K_CODES 1024
#define B_SZ   16
#define SPAT   216       // 6*6*6
#define VOX    13824     // 24^3
#define OUT_ZQ (B_SZ * C_DIM * SPAT)   // 884736
#define OUT_LOSS OUT_ZQ
#define OUT_IDX (OUT_ZQ + 1)

// ---------------- device scratch ----------------
__device__ float g_zn[N_ROWS * C_DIM];
__device__ __nv_bfloat16 g_z0[N_ROWS * C_DIM];
__device__ __nv_bfloat16 g_z1[N_ROWS * C_DIM];
__device__ float g_en[K_CODES * C_DIM];
__device__ __nv_bfloat16 g_e0[K_CODES * C_DIM];
__device__ __nv_bfloat16 g_e1[K_CODES * C_DIM];
__device__ float g_aff[N_ROWS * K_CODES];
__device__ unsigned long long g_pat[N_ROWS];
__device__ float g_avgp[K_CODES];
__device__ float g_sums[8];   // 0: SSE, 1: entropy sum, 2: sumW, 3: sumWcos
__device__ int g_ctr;

// ---------------- helpers ----------------
__device__ __forceinline__ float bsum256(float v, float* red) {
    #pragma unroll
    for (int o = 16; o; o >>= 1) v += __shfl_xor_sync(0xffffffffu, v, o);
    __syncthreads();
    if ((threadIdx.x & 31) == 0) red[threadIdx.x >> 5] = v;
    __syncthreads();
    float s = 0.f;
    #pragma unroll
    for (int w = 0; w < 8; w++) s += red[w];
    return s;
}

__device__ __forceinline__ float fexp(float d) {   // e^d for d <= 0
    float r;
    asm("ex2.approx.f32 %0, %1;" : "=f"(r) : "f"(d * 1.4426950408889634f));
    return r;
}

__device__ __forceinline__ void ldsm_x4(uint32_t& r0, uint32_t& r1, uint32_t& r2, uint32_t& r3, uint32_t addr) {
    asm volatile("ldmatrix.sync.aligned.m8n8.x4.shared.b16 {%0,%1,%2,%3}, [%4];"
                 : "=r"(r0), "=r"(r1), "=r"(r2), "=r"(r3) : "r"(addr));
}
__device__ __forceinline__ void mma_bf16(float* c, uint32_t a0, uint32_t a1, uint32_t a2, uint32_t a3,
                                         uint32_t b0, uint32_t b1) {
    asm volatile("mma.sync.aligned.m16n8k16.row.col.f32.bf16.bf16.f32 "
                 "{%0,%1,%2,%3}, {%4,%5,%6,%7}, {%8,%9}, {%0,%1,%2,%3};"
                 : "+f"(c[0]), "+f"(c[1]), "+f"(c[2]), "+f"(c[3])
                 : "r"(a0), "r"(a1), "r"(a2), "r"(a3), "r"(b0), "r"(b1));
}

__device__ __forceinline__ void bsplit2(float x, __nv_bfloat16& b0, __nv_bfloat16& b1) {
    b0 = __float2bfloat16_rn(x);
    b1 = __float2bfloat16_rn(x - __bfloat162float(b0));
}

// =======================================================================
// K_PRE: pattern (blocks 0..215) | norm_z (216..343) | norm_cb (344..1367)
// =======================================================================
#define NZ_SCH 27
#define NZ_PAD 29
#define PRE_NZ_BYTES (256 * NZ_PAD * 4 + 8 * 32 * 4 + NZ_SCH * 4 + 64)
__global__ __launch_bounds__(256) void k_pre(const float* __restrict__ inp,
                                             const float* __restrict__ z_e,
                                             const float* __restrict__ cb) {
    __shared__ __align__(16) char sraw[PRE_NZ_BYTES];
    int tid = threadIdx.x;
    int bid = blockIdx.x;

    if (bid < 216) {
        // ---- patterns: 4 voxels/thread, 16 patterns/block, MLP-8 ----
        unsigned char* sb = (unsigned char*)sraw;
        int v0 = (bid * 256 + tid) * 4;
        int b = v0 / VOX, s = v0 % VOX;
        const float* p = inp + (size_t)b * 32 * VOX + s;
        float4 x0 = *(const float4*)p;
        float m0 = -1e30f, m1 = -1e30f, m2 = -1e30f, m3 = -1e30f;
        #pragma unroll 8
        for (int c = 1; c < 32; c++) {
            float4 y = *(const float4*)&p[c * VOX];
            m0 = fmaxf(m0, y.x);
            m1 = fmaxf(m1, y.y);
            m2 = fmaxf(m2, y.z);
            m3 = fmaxf(m3, y.w);
        }
        unsigned bits = (m0 > x0.x ? 1u : 0u) | (m1 > x0.y ? 2u : 0u) |
                        (m2 > x0.z ? 4u : 0u) | (m3 > x0.w ? 8u : 0u);
        sb[tid] = (unsigned char)bits;
        __syncthreads();
        if (tid < 16) {
            unsigned long long pat = 0;
            #pragma unroll
            for (int i = 0; i < 16; i++)
                pat |= (unsigned long long)sb[tid * 16 + i] << (4 * i);
            g_pat[bid * 16 + tid] = pat;
        }
        if (bid == 0) {
            for (int i = tid; i < K_CODES; i += 256) g_avgp[i] = 0.f;
            if (tid < 8) g_sums[tid] = 0.f;
            if (tid == 0) g_ctr = 0;
        }
    } else if (bid < 344) {
        // ---- norm_z ----
        int nb = bid - 216;
        float* sm = (float*)sraw;
        float* pnormf = sm + 256 * NZ_PAD;
        float* norm = pnormf + 8 * 32;
        int b = nb >> 3;
        int s0 = (nb & 7) * NZ_SCH;
        const float* src = z_e + (size_t)b * C_DIM * SPAT + s0;
        for (int i = tid; i < 256 * NZ_SCH; i += 256) {
            int c = i / NZ_SCH, s = i - c * NZ_SCH;
            sm[c * NZ_PAD + s] = src[c * SPAT + s];
        }
        __syncthreads();
        int cg = tid >> 5, lane = tid & 31;
        if (lane < NZ_SCH) {
            float acc = 0.f;
            #pragma unroll
            for (int k = 0; k < 32; k++) {
                float v = sm[(cg * 32 + k) * NZ_PAD + lane];
                acc += v * v;
            }
            pnormf[cg * 32 + lane] = acc;
        }
        __syncthreads();
        if (tid < NZ_SCH) {
            float a = 0.f;
            #pragma unroll
            for (int g = 0; g < 8; g++) a += pnormf[g * 32 + tid];
            norm[tid] = fmaxf(sqrtf(a), 1e-12f);
        }
        __syncthreads();
        for (int i = tid; i < 256 * NZ_SCH; i += 256) {
            int s = i >> 8, c = i & 255;
            float vn = sm[c * NZ_PAD + s] / norm[s];
            int n = b * SPAT + s0 + s;
            g_zn[n * C_DIM + c] = vn;
            __nv_bfloat16 b0, b1;
            bsplit2(vn, b0, b1);
            g_z0[n * C_DIM + c] = b0;
            g_z1[n * C_DIM + c] = b1;
        }
    } else {
        // ---- norm_cb ----
        int k = bid - 344;
        float* red = (float*)sraw;
        float v = cb[k * C_DIM + tid];
        float ss = bsum256(v * v, red);
        float vn = v / fmaxf(sqrtf(ss), 1e-12f);
        g_en[k * C_DIM + tid] = vn;
        __nv_bfloat16 b0, b1;
        bsplit2(vn, b0, b1);
        g_e0[k * C_DIM + tid] = b0;
        g_e1[k * C_DIM + tid] = b1;
    }
}

// =======================================================================
// K_MID: affinity (blocks 0..431) | ham triangle (432..1187, prefetch)  [frozen]
// =======================================================================
#define AF_PAD 40
#define HM_PAD 72
#define MID_BYTES 31232
__global__ __launch_bounds__(256) void k_mid() {
    __shared__ __align__(16) char sraw[MID_BYTES];
    int tid = threadIdx.x;
    int bid = blockIdx.x;
    int warp = tid >> 5, lane = tid & 31;
    int wi = warp >> 2, wj = warp & 3;

    if (bid < 432) {
        __nv_bfloat16* As0 = (__nv_bfloat16*)sraw;
        __nv_bfloat16* As1 = As0 + 64 * AF_PAD;
        __nv_bfloat16* Bs0 = As1 + 64 * AF_PAD;
        __nv_bfloat16* Bs1 = Bs0 + 128 * AF_PAD;
        __nv_bfloat16* Asp[2] = {As0, As1};
        __nv_bfloat16* Bsp[2] = {Bs0, Bs1};

        int rowBase = (bid >> 3) * 64;
        int colBase = (bid & 7) * 128;
        const __nv_bfloat16* Az0 = g_z0 + rowBase * C_DIM;
        const __nv_bfloat16* Az1 = g_z1 + rowBase * C_DIM;
        const __nv_bfloat16* Be0 = g_e0 + colBase * C_DIM;
        const __nv_bfloat16* Be1 = g_e1 + colBase * C_DIM;

        uint32_t sA[2], sB[2];
        sA[0] = (uint32_t)__cvta_generic_to_shared(As0);
        sA[1] = (uint32_t)__cvta_generic_to_shared(As1);
        sB[0] = (uint32_t)__cvta_generic_to_shared(Bs0);
        sB[1] = (uint32_t)__cvta_generic_to_shared(Bs1);

        int aspl[2], arow[2], apart[2];
        int bspl[4], brow[4], bpart[4];
        #pragma unroll
        for (int i = 0; i < 2; i++) {
            int g = tid + i * 256;
            aspl[i] = g >> 8; int idx = g & 255;
            arow[i] = idx >> 2; apart[i] = idx & 3;
        }
        #pragma unroll
        for (int i = 0; i < 4; i++) {
            int h = tid + i * 256;
            bspl[i] = h >> 9; int idx = h & 511;
            brow[i] = idx >> 2; bpart[i] = idx & 3;
        }

        uint4 pf[6];
        auto loadregs = [&](int kc) {
            #pragma unroll
            for (int i = 0; i < 2; i++) {
                const __nv_bfloat16* base = aspl[i] ? Az1 : Az0;
                pf[i] = *(const uint4*)&base[arow[i] * C_DIM + kc + apart[i] * 8];
            }
            #pragma unroll
            for (int i = 0; i < 4; i++) {
                const __nv_bfloat16* base = bspl[i] ? Be1 : Be0;
                pf[2 + i] = *(const uint4*)&base[brow[i] * C_DIM + kc + bpart[i] * 8];
            }
        };
        auto storeregs = [&]() {
            #pragma unroll
            for (int i = 0; i < 2; i++)
                *(uint4*)&Asp[aspl[i]][arow[i] * AF_PAD + apart[i] * 8] = pf[i];
            #pragma unroll
            for (int i = 0; i < 4; i++)
                *(uint4*)&Bsp[bspl[i]][brow[i] * AF_PAD + bpart[i] * 8] = pf[2 + i];
        };

        float acc[2][4][4] = {};
        loadregs(0);
        storeregs();
        __syncthreads();

        for (int c = 0; c < 8; c++) {
            if (c < 7) loadregs((c + 1) * 32);
            #pragma unroll
            for (int ks = 0; ks < 2; ks++) {
                int k0 = ks * 16;
                uint32_t a[2][2][4], b[2][2][4];
                #pragma unroll
                for (int s = 0; s < 2; s++) {
                    #pragma unroll
                    for (int mt = 0; mt < 2; mt++) {
                        int rb = wi * 32 + mt * 16;
                        uint32_t addr = sA[s] + ((rb + (lane & 15)) * AF_PAD + k0 + (lane >> 4) * 8) * 2;
                        ldsm_x4(a[s][mt][0], a[s][mt][1], a[s][mt][2], a[s][mt][3], addr);
                    }
                    #pragma unroll
                    for (int ng = 0; ng < 2; ng++) {
                        int row = wj * 32 + ng * 16 + (lane & 7) + ((lane >> 4) << 3);
                        int koff = k0 + ((lane >> 3) & 1) * 8;
                        uint32_t addr = sB[s] + (row * AF_PAD + koff) * 2;
                        ldsm_x4(b[s][ng][0], b[s][ng][1], b[s][ng][2], b[s][ng][3], addr);
                    }
                }
                #pragma unroll
                for (int mt = 0; mt < 2; mt++)
                    #pragma unroll
                    for (int nt = 0; nt < 4; nt++) {
                        int ng = nt >> 1, off = (nt & 1) * 2;
                        float* cc = acc[mt][nt];
                        mma_bf16(cc, a[0][mt][0], a[0][mt][1], a[0][mt][2], a[0][mt][3],
                                 b[0][ng][off], b[0][ng][off + 1]);
                        mma_bf16(cc, a[0][mt][0], a[0][mt][1], a[0][mt][2], a[0][mt][3],
                                 b[1][ng][off], b[1][ng][off + 1]);
                        mma_bf16(cc, a[1][mt][0], a[1][mt][1], a[1][mt][2], a[1][mt][3],
                                 b[0][ng][off], b[0][ng][off + 1]);
                    }
            }
            __syncthreads();
            if (c < 7) {
                storeregs();
                __syncthreads();
            }
        }

        #pragma unroll
        for (int mt = 0; mt < 2; mt++) {
            #pragma unroll
            for (int nt = 0; nt < 4; nt++) {
                int i0 = rowBase + wi * 32 + mt * 16 + (lane >> 2);
                int j0 = colBase + wj * 32 + nt * 8 + (lane & 3) * 2;
                *(float2*)&g_aff[i0 * K_CODES + j0] = make_float2(acc[mt][nt][0], acc[mt][nt][1]);
                *(float2*)&g_aff[(i0 + 8) * K_CODES + j0] = make_float2(acc[mt][nt][2], acc[mt][nt][3]);
            }
        }
    } else {
        int id = bid - 432;
        int jt = (int)((sqrtf(4.f * id + 1.f) - 1.f) * 0.5f);
        while (jt * jt + jt > id) jt--;
        while ((jt + 1) * (jt + 1) + (jt + 1) <= id) jt++;
        int it = id - (jt * jt + jt);

        __nv_bfloat16* Ahs = (__nv_bfloat16*)sraw;
        __nv_bfloat16* Bhs = Ahs + 64 * HM_PAD;
        unsigned long long* spi = (unsigned long long*)(Bhs + 128 * HM_PAD);
        unsigned long long* spj = spi + 64;
        float* red = (float*)(spj + 128);

        const __nv_bfloat16* Ag = g_z0 + it * 64 * C_DIM;
        const __nv_bfloat16* Bg = g_z0 + jt * 128 * C_DIM;
        if (tid < 64)        spi[tid] = g_pat[it * 64 + tid];
        else if (tid < 192)  spj[tid - 64] = g_pat[jt * 128 + tid - 64];

        uint32_t sA = (uint32_t)__cvta_generic_to_shared(Ahs);
        uint32_t sB = (uint32_t)__cvta_generic_to_shared(Bhs);
        float acc[2][4][4] = {};

        int hisB[6], hrow[6], hpart[6];
        #pragma unroll
        for (int i = 0; i < 6; i++) {
            int g = tid + i * 256;
            if (g < 512) { hisB[i] = 0; hrow[i] = g >> 3; hpart[i] = g & 7; }
            else { int h = g - 512; hisB[i] = 1; hrow[i] = h >> 3; hpart[i] = h & 7; }
        }
        uint4 hpf[6];
        auto hload = [&](int kc) {
            #pragma unroll
            for (int i = 0; i < 6; i++) {
                const __nv_bfloat16* base = hisB[i] ? Bg : Ag;
                hpf[i] = *(const uint4*)&base[hrow[i] * C_DIM + kc + hpart[i] * 8];
            }
        };
        auto hstore = [&]() {
            #pragma unroll
            for (int i = 0; i < 6; i++) {
                __nv_bfloat16* dst = hisB[i] ? Bhs : Ahs;
                *(uint4*)&dst[hrow[i] * HM_PAD + hpart[i] * 8] = hpf[i];
            }
        };

        hload(0);
        hstore();
        __syncthreads();

        for (int c = 0; c < 4; c++) {
            if (c < 3) hload((c + 1) * 64);
            #pragma unroll
            for (int ks = 0; ks < 4; ks++) {
                int k0 = ks * 16;
                uint32_t a[2][4], b[2][4];
                #pragma unroll
                for (int mt = 0; mt < 2; mt++) {
                    int rb = wi * 32 + mt * 16;
                    uint32_t addr = sA + ((rb + (lane & 15)) * HM_PAD + k0 + (lane >> 4) * 8) * 2;
                    ldsm_x4(a[mt][0], a[mt][1], a[mt][2], a[mt][3], addr);
                }
                #pragma unroll
                for (int ng = 0; ng < 2; ng++) {
                    int row = wj * 32 + ng * 16 + (lane & 7) + ((lane >> 4) << 3);
                    int koff = k0 + ((lane >> 3) & 1) * 8;
                    uint32_t addr = sB + (row * HM_PAD + koff) * 2;
                    ldsm_x4(b[ng][0], b[ng][1], b[ng][2], b[ng][3], addr);
                }
                #pragma unroll
                for (int mt = 0; mt < 2; mt++)
                    #pragma unroll
                    for (int nt = 0; nt < 4; nt++) {
                        int ng = nt >> 1, off = (nt & 1) * 2;
                        mma_bf16(acc[mt][nt], a[mt][0], a[mt][1], a[mt][2], a[mt][3],
                                 b[ng][off], b[ng][off + 1]);
                    }
            }
            __syncthreads();
            if (c < 3) {
                hstore();
                __syncthreads();
            }
        }

        float ws = 0.f, wc = 0.f;
        #pragma unroll
        for (int mt = 0; mt < 2; mt++) {
            #pragma unroll
            for (int nt = 0; nt < 4; nt++) {
                int li0 = wi * 32 + mt * 16 + (lane >> 2);
                int lj0 = wj * 32 + nt * 8 + (lane & 3) * 2;
                #pragma unroll
                for (int hh = 0; hh < 2; hh++) {
                    int li = li0 + hh * 8;
                    int gi = it * 64 + li;
                    unsigned long long pi = spi[li];
                    #pragma unroll
                    for (int jj = 0; jj < 2; jj++) {
                        int lj = lj0 + jj;
                        int gj = jt * 128 + lj;
                        int h = __popcll(pi ^ spj[lj]);
                        if (gj > gi && h <= 5) {
                            float w = 1.0f - (float)h * (1.0f / 64.0f);
                            ws += w;
                            wc += w * acc[mt][nt][hh * 2 + jj];
                        }
                    }
                }
            }
        }
        float wsb = bsum256(ws * 2.0f, red);
        float wcb = bsum256(wc * 2.0f, red);
        if (tid == 0) {
            atomicAdd(&g_sums[2], wsb);
            atomicAdd(&g_sums[3], wcb);
        }
    }
}

// =======================================================================
// K_POST: warp-per-row (zero per-row barriers) + last-block final combine
// =======================================================================
#define ROWS_PB 8
__global__ __launch_bounds__(256) void k_post(float* __restrict__ out) {
    int n0 = blockIdx.x * ROWS_PB, t = threadIdx.x;
    int lane = t & 31, w = t >> 5;
    int n = n0 + w;                      // this warp's row
    __shared__ float s_avgp[K_CODES];
    __shared__ float s_ent[8], s_sse[8];
    __shared__ float zqs[ROWS_PB][C_DIM];
    __shared__ float redA[8];
    __shared__ int slast;

    // zero block-local avgp accumulator
    #pragma unroll
    for (int q = 0; q < 4; q++) s_avgp[t + q * 256] = 0.f;
    __syncthreads();

    // ---- load this warp's row: lane handles codes lane + 32q ----
    float fa[32];
    const float* arow = g_aff + (size_t)n * K_CODES + lane;
    #pragma unroll
    for (int q = 0; q < 32; q++)
        fa[q] = arow[q * 32] * 100.0f;

    // thread-local argmax (ascending q => first occurrence = min index)
    float m = fa[0]; int mi = lane;
    #pragma unroll
    for (int q = 1; q < 32; q++)
        if (fa[q] > m) { m = fa[q]; mi = lane + q * 32; }
    // warp argmax, min-index tiebreak
    #pragma unroll
    for (int o = 16; o; o >>= 1) {
        float om = __shfl_xor_sync(0xffffffffu, m, o);
        int   oi = __shfl_xor_sync(0xffffffffu, mi, o);
        if (om > m || (om == m && oi < mi)) { m = om; mi = oi; }
    }
    float bm = m; int bidx = mi;     // same in all lanes

    // softmax stats (e overwrites fa)
    float se = 0.f, te = 0.f;
    #pragma unroll
    for (int q = 0; q < 32; q++) {
        float d = fa[q] - bm;
        float e = fexp(d);
        fa[q] = e;
        se += e;
        te += e * d;
    }
    #pragma unroll
    for (int o = 16; o; o >>= 1) {
        se += __shfl_xor_sync(0xffffffffu, se, o);
        te += __shfl_xor_sync(0xffffffffu, te, o);
    }
    float Z = se, T = te;
    float invZ = 1.0f / Z;

    // accumulate avg_probs into block-local smem (spread-address ATOMS)
    #pragma unroll
    for (int q = 0; q < 32; q++)
        atomicAdd(&s_avgp[lane + q * 32], fa[q] * invZ);

    if (lane == 0) {
        s_ent[w] = logf(Z) - T / Z;
        out[OUT_IDX + n] = (float)bidx;
    }

    // z_q channels: lane handles c = lane + 32j (coalesced, conflict-free)
    float ss = 0.f;
    const float* enr = g_en + (size_t)bidx * C_DIM + lane;
    const float* znr = g_zn + (size_t)n * C_DIM + lane;
    #pragma unroll
    for (int j = 0; j < 8; j++) {
        float zq = enr[j * 32];
        float zn = znr[j * 32];
        zqs[w][lane + j * 32] = zq;
        float dd = zq - zn;
        ss += dd * dd;
    }
    #pragma unroll
    for (int o = 16; o; o >>= 1) ss += __shfl_xor_sync(0xffffffffu, ss, o);
    if (lane == 0) s_sse[w] = ss;
    __syncthreads();

    // flush avg_probs to global (1024 atomics per block, unchanged total)
    const float invN = 1.0f / (float)N_ROWS;
    #pragma unroll
    for (int q = 0; q < 4; q++)
        atomicAdd(&g_avgp[t + q * 256], s_avgp[t + q * 256] * invN);
    if (t == 0) {
        float eacc = 0.f, sacc = 0.f;
        #pragma unroll
        for (int i = 0; i < 8; i++) { eacc += s_ent[i]; sacc += s_sse[i]; }
        atomicAdd(&g_sums[1], eacc);
        atomicAdd(&g_sums[0], sacc);
    }

    // coalesced z_q write
    {
        int b = n0 / SPAT, s0 = n0 % SPAT;
        float* dst = out + ((size_t)b * C_DIM) * SPAT + s0;
        for (int i = t; i < C_DIM * ROWS_PB; i += 256) {
            int c = i >> 3, rr = i & 7;
            dst[c * SPAT + rr] = zqs[rr][c];
        }
    }

    // ---- last block performs final combine ----
    __threadfence();
    if (t == 0) {
        int old = atomicAdd(&g_ctr, 1);
        slast = (old == (int)gridDim.x - 1) ? 1 : 0;
    }
    __syncthreads();
    if (slast) {
        __threadfence();
        float v = 0.f;
        #pragma unroll
        for (int q = 0; q < 4; q++) {
            float p = g_avgp[t + q * 256];
            v += p * logf(p + 1e-5f);
        }
        float s = bsum256(v, redA);
        if (t == 0) {
            float sseT = g_sums[0];
            float sent = g_sums[1];
            float sw   = g_sums[2];
            float swc  = g_sums[3];
            float codebook_loss = sseT / (float)(N_ROWS * C_DIM);
            float commit_loss   = 0.25f * codebook_loss;
            float sample_entropy = sent / (float)N_ROWS;
            float avg_entropy    = -s;
            float ent_loss = 0.1f * (sample_entropy - avg_entropy);
            float ham_loss = (sw - swc) / (sw + 1e-8f);
            out[OUT_LOSS] = codebook_loss + commit_loss + ent_loss + ham_loss;
        }
    }
}

// ---------------- launch ----------------
extern "C" void kernel_launch(void* const* d_in, const int* in_sizes, int n_in,
                              void* d_out, int out_size) {
    const float* input_blocks = (const float*)d_in[0];
    const float* z_e          = (const float*)d_in[1];
    const float* codebook     = (const float*)d_in[2];
    float* out = (float*)d_out;

    k_pre<<<1368, 256>>>(input_blocks, z_e, codebook);
    k_mid<<<1188, 256>>>();
    k_post<<<N_ROWS / ROWS_PB, 256>>>(out);
}